// round 6
// baseline (speedup 1.0000x reference)
#include <cuda_runtime.h>
#include <cuda_bf16.h>
#include <math.h>
#include <stdint.h>

#define BATCH 8
#define CH 64
#define HH 512
#define WW 512
#define LL (HH*WW)
#define DSTATE 16
#define CUT 2048
#define BN_EPS 1e-5f

// scratch
__device__ float g_xp[(size_t)BATCH*CH*LL];
__device__ float g_xc[(size_t)BATCH*CH*LL];
__device__ float g_Bp[BATCH*DSTATE*CUT];
__device__ float g_Sp[BATCH*DSTATE*CUT];
__device__ float g_S [BATCH*DSTATE];

// pre-swizzled bf16 hi/lo weight tiles
__device__ __align__(16) unsigned char g_WinH[8192],  g_WinL[8192];
__device__ __align__(16) unsigned char g_WgH[16384],  g_WgL[16384];
__device__ __align__(16) unsigned char g_WoH[8192],   g_WoL[8192];

__device__ __forceinline__ float fsig(float x){ return 1.0f/(1.0f+__expf(-x)); }
__device__ __forceinline__ float ftanh(float x){
  x = fminf(fmaxf(x, -15.f), 15.f);
  float e = __expf(2.f*x);
  return __fdividef(e-1.f, e+1.f);
}

#define SW128(o) ((o) ^ (((o)>>3)&0x70))

__device__ __forceinline__ uint32_t smem_u32(const void* p){
  uint32_t a;
  asm("{ .reg .u64 t; cvta.to.shared.u64 t, %1; cvt.u32.u64 %0, t; }"
      : "=r"(a) : "l"(p));
  return a;
}
__device__ __forceinline__ void ldsm4(unsigned r[4], uint32_t a){
  asm volatile("ldmatrix.sync.aligned.m8n8.x4.shared.b16 {%0,%1,%2,%3}, [%4];"
    : "=r"(r[0]),"=r"(r[1]),"=r"(r[2]),"=r"(r[3]) : "r"(a));
}
__device__ __forceinline__ void ldsm2(unsigned r[2], uint32_t a){
  asm volatile("ldmatrix.sync.aligned.m8n8.x2.shared.b16 {%0,%1}, [%2];"
    : "=r"(r[0]),"=r"(r[1]) : "r"(a));
}
__device__ __forceinline__ void mma16816(float d[4], const unsigned a[4], const unsigned b[2]){
  asm volatile("mma.sync.aligned.m16n8k16.row.col.f32.bf16.bf16.f32 "
    "{%0,%1,%2,%3}, {%4,%5,%6,%7}, {%8,%9}, {%0,%1,%2,%3};"
    : "+f"(d[0]),"+f"(d[1]),"+f"(d[2]),"+f"(d[3])
    : "r"(a[0]),"r"(a[1]),"r"(a[2]),"r"(a[3]), "r"(b[0]),"r"(b[1]));
}

// fast truncation split: hi = top-16-bit truncation, lo = rn(exact residual)
__device__ __forceinline__ void split2t(float v0, float v1, unsigned& hi, unsigned& lo){
  unsigned u0 = __float_as_uint(v0), u1 = __float_as_uint(v1);
  unsigned h;
  asm("prmt.b32 %0, %1, %2, 0x7632;" : "=r"(h) : "r"(u0), "r"(u1));
  float r0 = v0 - __uint_as_float(u0 & 0xFFFF0000u);
  float r1 = v1 - __uint_as_float(u1 & 0xFFFF0000u);
  unsigned l;
  asm("cvt.rn.bf16x2.f32 %0, %1, %2;" : "=r"(l) : "f"(r1), "f"(r0));
  hi = h; lo = l;
}

// ---------------------------------------------------------------------------
// K0: one-time weight prep
// ---------------------------------------------------------------------------
__global__ void k_prep(const float* __restrict__ w_in,
                       const float* __restrict__ wg,
                       const float* __restrict__ wo)
{
  const int tid = threadIdx.x;
  for (int idx=tid; idx<4096; idx+=256){
    int n = idx>>6, k = idx&63;
    unsigned off = SW128((unsigned)(n*128 + k*2));
    { float v = w_in[idx];
      float h = __bfloat162float(__float2bfloat16_rn(v));
      *(__nv_bfloat16*)(g_WinH+off) = __float2bfloat16_rn(v);
      *(__nv_bfloat16*)(g_WinL+off) = __float2bfloat16_rn(v-h); }
    { float v = wo[idx];
      float h = __bfloat162float(__float2bfloat16_rn(v));
      *(__nv_bfloat16*)(g_WoH+off) = __float2bfloat16_rn(v);
      *(__nv_bfloat16*)(g_WoL+off) = __float2bfloat16_rn(v-h); }
  }
  for (int idx=tid; idx<8192; idx+=256){
    int n = idx>>6, k = idx&63;
    unsigned off = SW128((unsigned)(n*128 + k*2));
    float v = wg[idx];
    float h = __bfloat162float(__float2bfloat16_rn(v));
    *(__nv_bfloat16*)(g_WgH+off) = __float2bfloat16_rn(v);
    *(__nv_bfloat16*)(g_WgL+off) = __float2bfloat16_rn(v-h);
  }
}

// ---------------------------------------------------------------------------
// K1: xp = silu(bn(w_in @ x)) — mma.sync bf16-split. 256 px/block, 256 thr.
// ---------------------------------------------------------------------------
__global__ __launch_bounds__(256,2) void k_inproj(
    const float* __restrict__ x,
    const float* __restrict__ gin, const float* __restrict__ bin)
{
  extern __shared__ char dynraw[];
  char* base = (char*)(((uintptr_t)dynraw + 1023) & ~(uintptr_t)1023);
  char* Ahi = base;            // 32KB
  char* Alo = base + 32768;    // 32KB
  char* Whi = base + 65536;    // 8KB
  char* Wlo = base + 73728;    // 8KB
  __shared__ float sg[64], sb[64];

  const int tid = threadIdx.x, lane = tid&31, warp = tid>>5;
  const int b = blockIdx.y;
  const long p0 = (long)blockIdx.x*256;

  for (int idx=tid; idx<512; idx+=256){
    ((uint4*)Whi)[idx] = ((const uint4*)g_WinH)[idx];
    ((uint4*)Wlo)[idx] = ((const uint4*)g_WinL)[idx];
  }
  if (tid<64){ sg[tid]=gin[tid]*rsqrtf(1.f+BN_EPS); sb[tid]=bin[tid]; }

  { // A staging
    const float* xb = x + (long)b*CH*LL + p0 + tid;
    #pragma unroll
    for (int kb=0;kb<8;kb++){
      unsigned h[4], l[4];
      #pragma unroll
      for (int j=0;j<4;j++)
        split2t(xb[(long)(8*kb+2*j)*LL], xb[(long)(8*kb+2*j+1)*LL], h[j], l[j]);
      unsigned off = SW128((unsigned)(tid*128 + kb*16));
      *(uint4*)(Ahi+off) = make_uint4(h[0],h[1],h[2],h[3]);
      *(uint4*)(Alo+off) = make_uint4(l[0],l[1],l[2],l[3]);
    }
  }
  __syncthreads();

  const uint32_t AhiB=smem_u32(Ahi), AloB=smem_u32(Alo),
                 WhiB=smem_u32(Whi), WloB=smem_u32(Wlo);
  float acc[2][8][4];
  #pragma unroll
  for (int mt=0;mt<2;mt++)
    #pragma unroll
    for (int nt=0;nt<8;nt++)
      #pragma unroll
      for (int r=0;r<4;r++) acc[mt][nt][r]=0.f;

  const int Mb = warp*32;
  const int arow = (lane&7) + ((lane>>3)&1)*8;
  const int achk = lane>>4;
  const int brow = lane&7;
  const int bchk = (lane>>3)&1;

  #pragma unroll
  for (int ks=0; ks<4; ks++){
    unsigned ah[2][4], al[2][4];
    #pragma unroll
    for (int mt=0; mt<2; mt++){
      unsigned off = SW128((unsigned)((Mb+16*mt+arow)*128 + (2*ks+achk)*16));
      ldsm4(ah[mt], AhiB+off);
      ldsm4(al[mt], AloB+off);
    }
    #pragma unroll
    for (int nt=0; nt<8; nt++){
      unsigned boff = SW128((unsigned)((8*nt+brow)*128 + (2*ks+bchk)*16));
      unsigned bh[2], bl[2];
      ldsm2(bh, WhiB+boff);
      ldsm2(bl, WloB+boff);
      #pragma unroll
      for (int mt=0;mt<2;mt++){
        mma16816(acc[mt][nt], ah[mt], bh);
        mma16816(acc[mt][nt], al[mt], bh);
        mma16816(acc[mt][nt], ah[mt], bl);
      }
    }
  }
  __syncthreads();

  float* so = (float*)base;   // [64][268]
  #pragma unroll
  for (int mt=0;mt<2;mt++){
    int m = Mb + 16*mt + (lane>>2);
    #pragma unroll
    for (int nt=0;nt<8;nt++){
      int n = 8*nt + 2*(lane&3);
      so[n*268 + m]        = acc[mt][nt][0];
      so[(n+1)*268 + m]    = acc[mt][nt][1];
      so[n*268 + m + 8]    = acc[mt][nt][2];
      so[(n+1)*268 + m + 8]= acc[mt][nt][3];
    }
  }
  __syncthreads();

  float* dst = g_xp + (long)b*CH*LL + p0;
  #pragma unroll
  for (int r=0;r<16;r++){
    int f4 = tid + r*256;
    int ch = f4>>6, px = (f4&63)<<2;
    float4 v = *(float4*)(so + ch*268 + px);
    float sc = sg[ch], be = sb[ch];
    v.x = fmaf(v.x,sc,be); v.y = fmaf(v.y,sc,be);
    v.z = fmaf(v.z,sc,be); v.w = fmaf(v.w,sc,be);
    float4 o = make_float4(v.x*fsig(v.x), v.y*fsig(v.y), v.z*fsig(v.z), v.w*fsig(v.w));
    *(float4*)(dst + (long)ch*LL + px) = o;
  }
}

// ---------------------------------------------------------------------------
// K2: depthwise 3x3 + BN + SiLU
// ---------------------------------------------------------------------------
__global__ __launch_bounds__(128) void k_dwconv(
    const float* __restrict__ wdw, const float* __restrict__ gcv,
    const float* __restrict__ bcv)
{
  __shared__ float s[18*512];
  const int tid = threadIdx.x;
  const int b = blockIdx.z, c = blockIdx.y, h0 = blockIdx.x*16;
  const float* xpc = g_xp + (long)(b*CH+c)*LL;

  #pragma unroll
  for (int r=0;r<18;r++){
    int hh = h0 - 1 + r;
    float4 v = make_float4(0.f,0.f,0.f,0.f);
    if (hh >= 0 && hh < HH) v = *(const float4*)(xpc + (long)hh*WW + (tid<<2));
    *(float4*)(s + r*512 + (tid<<2)) = v;
  }
  __syncthreads();

  const float k0=wdw[c*9+0], k1=wdw[c*9+1], k2=wdw[c*9+2],
              k3=wdw[c*9+3], k4=wdw[c*9+4], k5=wdw[c*9+5],
              k6=wdw[c*9+6], k7=wdw[c*9+7], k8=wdw[c*9+8];
  const float rs = rsqrtf(1.0f+BN_EPS);
  const float sc = gcv[c]*rs, be = bcv[c];
  const int w = tid<<2;
  float* dst = g_xc + (long)(b*CH+c)*LL + (long)h0*WW + w;

  for (int r=0;r<16;r++){
    float in[3][6];
    #pragma unroll
    for (int dy=0;dy<3;dy++){
      const float* row = s + (r+dy)*512;
      in[dy][0] = (w>0)? row[w-1] : 0.f;
      float4 m = *(const float4*)(row + w);
      in[dy][1]=m.x; in[dy][2]=m.y; in[dy][3]=m.z; in[dy][4]=m.w;
      in[dy][5] = (w<508)? row[w+4] : 0.f;
    }
    float o[4];
    #pragma unroll
    for (int j=0;j<4;j++){
      float a = k0*in[0][j] + k1*in[0][j+1] + k2*in[0][j+2]
              + k3*in[1][j] + k4*in[1][j+1] + k5*in[1][j+2]
              + k6*in[2][j] + k7*in[2][j+1] + k8*in[2][j+2];
      a = fmaf(a, sc, be);
      o[j] = a*fsig(a);
    }
    *(float4*)(dst + (long)r*WW) = make_float4(o[0],o[1],o[2],o[3]);
  }
}

// ---------------------------------------------------------------------------
// K3: SSM pieces
// ---------------------------------------------------------------------------
__global__ __launch_bounds__(128) void k_bproj(const float* __restrict__ wB)
{
  const int b = blockIdx.y;
  const int k = blockIdx.x*128 + threadIdx.x;
  const float* xcb = g_xc + (long)b*CH*LL + k;
  float acc[16];
  #pragma unroll
  for (int s=0;s<16;s++) acc[s]=0.f;
  for (int i=0;i<64;i++){
    float xv = xcb[(long)i*LL];
    #pragma unroll
    for (int s=0;s<16;s++) acc[s] = fmaf(__ldg(&wB[s*64+i]), xv, acc[s]);
  }
  #pragma unroll
  for (int s=0;s<16;s++) g_Bp[(b*DSTATE+s)*CUT + k] = acc[s];
}

__global__ __launch_bounds__(256) void k_scan(const float* __restrict__ A)
{
  __shared__ float t[CUT];
  const int bs = blockIdx.x;
  const int s = bs & 15;
  const float a = A[s];
  for (int idx = threadIdx.x; idx < CUT; idx += 256)
    t[idx] = g_Bp[bs*CUT + idx] * expf(a * (float)idx);
  __syncthreads();
  if (threadIdx.x == 0){
    float acc = 0.f;
    for (int k=0;k<CUT;k++){ acc += t[k]; t[k] = acc; }
    g_S[bs] = acc;
  }
  __syncthreads();
  for (int idx = threadIdx.x; idx < CUT; idx += 256)
    g_Sp[bs*CUT + idx] = t[idx];
}

// ---------------------------------------------------------------------------
// K4: gate GEMM + combine + out GEMM. 256 px/block, 256 thr, warp owns m32.
// B-fragments reused across 2 m-tiles (halved ldsm). cvec folded in.
// ---------------------------------------------------------------------------
__global__ __launch_bounds__(256,1) void k_final(
  const float* __restrict__ wC, const float* __restrict__ Dv,
  const float* __restrict__ gg, const float* __restrict__ bg,
  const float* __restrict__ go, const float* __restrict__ bo,
  float* __restrict__ out)
{
  extern __shared__ char dynraw[];
  char* base = (char*)(((uintptr_t)dynraw + 1023) & ~(uintptr_t)1023);
  char* Ahi  = base;             // 32KB (xp, later xg)
  char* Alo  = base + 32768;     // 32KB
  char* WgHi = base + 65536;     // 16KB
  char* WgLo = base + 81920;     // 16KB
  char* WoHi = base + 98304;     // 8KB
  char* WoLo = base + 106496;    // 8KB  (total 112KB)
  __shared__ float s_gsc[128], s_gbe[128], s_dvec[64], s_cvec[64], s_osc[64], s_obe[64];
  __shared__ float s_wC[64*16];

  const int tid = threadIdx.x, lane = tid&31, warp = tid>>5;
  const int b = blockIdx.y;
  const long p0 = (long)blockIdx.x*256;
  const bool boundary = (p0 < CUT);
  const float rs = rsqrtf(1.0f+BN_EPS);

  for (int idx=tid; idx<1024; idx+=256){
    ((uint4*)WgHi)[idx] = ((const uint4*)g_WgH)[idx];
    ((uint4*)WgLo)[idx] = ((const uint4*)g_WgL)[idx];
  }
  for (int idx=tid; idx<512; idx+=256){
    ((uint4*)WoHi)[idx] = ((const uint4*)g_WoH)[idx];
    ((uint4*)WoLo)[idx] = ((const uint4*)g_WoL)[idx];
  }
  if (tid < 128){ s_gsc[tid] = gg[tid]*rs; s_gbe[tid] = bg[tid]; }
  for (int idx=tid; idx<1024; idx+=256) s_wC[idx] = wC[idx];
  if (tid < 64){
    s_dvec[tid] = Dv[tid];
    s_osc[tid]  = go[tid]*rs;
    s_obe[tid]  = bo[tid];
    float c = 0.f;
    #pragma unroll
    for (int s=0;s<16;s++) c = fmaf(wC[tid*16+s], g_S[b*16+s], c);
    s_cvec[tid] = c;
  }

  { // A staging: thread = pixel
    const float* xpb = g_xp + (long)b*CH*LL + p0 + tid;
    #pragma unroll
    for (int kb=0;kb<8;kb++){
      unsigned h[4], l[4];
      #pragma unroll
      for (int j=0;j<4;j++)
        split2t(xpb[(long)(8*kb+2*j)*LL], xpb[(long)(8*kb+2*j+1)*LL], h[j], l[j]);
      unsigned off = SW128((unsigned)(tid*128 + kb*16));
      *(uint4*)(Ahi+off) = make_uint4(h[0],h[1],h[2],h[3]);
      *(uint4*)(Alo+off) = make_uint4(l[0],l[1],l[2],l[3]);
    }
  }
  __syncthreads();

  const uint32_t AhiB=smem_u32(Ahi), AloB=smem_u32(Alo),
                 WgHiB=smem_u32(WgHi), WgLoB=smem_u32(WgLo),
                 WoHiB=smem_u32(WoHi), WoLoB=smem_u32(WoLo);
  const int Mb = warp*32;
  const int arow = (lane&7) + ((lane>>3)&1)*8;
  const int achk = lane>>4;
  const int brow = lane&7;
  const int bchk = (lane>>3)&1;

  // preload A fragments (xp): 2 m-tiles x 4 ks x hi/lo = 64 regs
  unsigned ah[2][4][4], al[2][4][4];
  #pragma unroll
  for (int mt=0; mt<2; mt++)
    #pragma unroll
    for (int ks=0; ks<4; ks++){
      unsigned aoff = SW128((unsigned)((Mb+16*mt+arow)*128 + (2*ks+achk)*16));
      ldsm4(ah[mt][ks], AhiB+aoff);
      ldsm4(al[mt][ks], AloB+aoff);
    }

  // gate GEMM + combine streamed per nt
  const float* xcb = g_xc + (long)b*CH*LL + p0;
  #pragma unroll
  for (int nt=0; nt<8; nt++){
    float accg[2][4] = {{0.f,0.f,0.f,0.f},{0.f,0.f,0.f,0.f}};
    float accs[2][4] = {{0.f,0.f,0.f,0.f},{0.f,0.f,0.f,0.f}};
    #pragma unroll
    for (int ks=0; ks<4; ks++){
      unsigned bgo = SW128((unsigned)((8*nt+brow)*128 + (2*ks+bchk)*16));
      unsigned bso = SW128((unsigned)((8*(nt+8)+brow)*128 + (2*ks+bchk)*16));
      unsigned bh[2], bl[2];
      ldsm2(bh, WgHiB+bgo); ldsm2(bl, WgLoB+bgo);
      #pragma unroll
      for (int mt=0;mt<2;mt++){
        mma16816(accg[mt], ah[mt][ks], bh);
        mma16816(accg[mt], al[mt][ks], bh);
        mma16816(accg[mt], ah[mt][ks], bl);
      }
      ldsm2(bh, WgHiB+bso); ldsm2(bl, WgLoB+bso);
      #pragma unroll
      for (int mt=0;mt<2;mt++){
        mma16816(accs[mt], ah[mt][ks], bh);
        mma16816(accs[mt], al[mt][ks], bh);
        mma16816(accs[mt], ah[mt][ks], bl);
      }
    }
    const int ch0 = 8*nt + 2*(lane&3), ch1 = ch0+1;
    const float dv0 = s_dvec[ch0], dv1 = s_dvec[ch1];
    #pragma unroll
    for (int mt=0; mt<2; mt++){
      #pragma unroll
      for (int rp=0; rp<2; rp++){
        const int pxl = Mb + 16*mt + (lane>>2) + rp*8;
        float base0, base1;
        if (boundary){
          const long p = p0 + pxl;
          float d0=0.f, d1=0.f;
          for (int s=0;s<16;s++){
            float sv = g_Sp[(b*DSTATE+s)*CUT + p];
            d0 = fmaf(s_wC[ch0*16+s], sv, d0);
            d1 = fmaf(s_wC[ch1*16+s], sv, d1);
          }
          base0=d0; base1=d1;
        } else { base0 = s_cvec[ch0]; base1 = s_cvec[ch1]; }
        float xc0 = xcb[(long)ch0*LL + pxl];
        float xc1 = xcb[(long)ch1*LL + pxl];
        float g0 = fmaf(accg[mt][2*rp],   s_gsc[ch0], s_gbe[ch0]);
        float g1 = fmaf(accg[mt][2*rp+1], s_gsc[ch1], s_gbe[ch1]);
        float h0 = fmaf(accs[mt][2*rp],   s_gsc[64+ch0], s_gbe[64+ch0]);
        float h1 = fmaf(accs[mt][2*rp+1], s_gsc[64+ch1], s_gbe[64+ch1]);
        float v0 = fsig(g0)*(fmaf(dv0, xc0, base0) + ftanh(h0));
        float v1 = fsig(g1)*(fmaf(dv1, xc1, base1) + ftanh(h1));
        unsigned hi, lo;
        split2t(v0, v1, hi, lo);
        unsigned off = SW128((unsigned)(pxl*128 + ch0*2));
        *(unsigned*)(Ahi+off) = hi;
        *(unsigned*)(Alo+off) = lo;
      }
    }
  }
  __syncwarp();   // rows [Mb, Mb+32) are warp-private

  // reload A fragments (xg)
  #pragma unroll
  for (int mt=0; mt<2; mt++)
    #pragma unroll
    for (int ks=0; ks<4; ks++){
      unsigned aoff = SW128((unsigned)((Mb+16*mt+arow)*128 + (2*ks+achk)*16));
      ldsm4(ah[mt][ks], AhiB+aoff);
      ldsm4(al[mt][ks], AloB+aoff);
    }

  // out GEMM
  float acc2[2][8][4];
  #pragma unroll
  for (int mt=0;mt<2;mt++)
    #pragma unroll
    for (int nt=0;nt<8;nt++)
      #pragma unroll
      for (int r=0;r<4;r++) acc2[mt][nt][r]=0.f;
  #pragma unroll
  for (int ks=0; ks<4; ks++){
    #pragma unroll
    for (int nt=0; nt<8; nt++){
      unsigned boff = SW128((unsigned)((8*nt+brow)*128 + (2*ks+bchk)*16));
      unsigned bh[2], bl[2];
      ldsm2(bh, WoHiB+boff);
      ldsm2(bl, WoLoB+boff);
      #pragma unroll
      for (int mt=0;mt<2;mt++){
        mma16816(acc2[mt][nt], ah[mt][ks], bh);
        mma16816(acc2[mt][nt], al[mt][ks], bh);
        mma16816(acc2[mt][nt], ah[mt][ks], bl);
      }
    }
  }
  __syncthreads();

  float* so = (float*)base;   // [64][260] = 66.6KB over Ahi/Alo/WgHi (dead)
  #pragma unroll
  for (int mt=0;mt<2;mt++){
    int m = Mb + 16*mt + (lane>>2);
    #pragma unroll
    for (int nt=0;nt<8;nt++){
      int n = 8*nt + 2*(lane&3);
      so[n*260 + m]        = acc2[mt][nt][0];
      so[(n+1)*260 + m]    = acc2[mt][nt][1];
      so[n*260 + m + 8]    = acc2[mt][nt][2];
      so[(n+1)*260 + m + 8]= acc2[mt][nt][3];
    }
  }
  __syncthreads();

  float* dst = out + (long)b*CH*LL + p0;
  #pragma unroll
  for (int r=0;r<16;r++){
    int f4 = tid + r*256;
    int ch = f4>>6, px = (f4&63)<<2;
    float4 v = *(float4*)(so + ch*260 + px);
    float sc = s_osc[ch], be = s_obe[ch];
    float4 o = make_float4(fmaf(v.x,sc,be), fmaf(v.y,sc,be),
                           fmaf(v.z,sc,be), fmaf(v.w,sc,be));
    *(float4*)(dst + (long)ch*LL + px) = o;
  }
}

// ---------------------------------------------------------------------------
extern "C" void kernel_launch(void* const* d_in, const int* in_sizes, int n_in,
                              void* d_out, int out_size)
{
  const float* x    = (const float*)d_in[0];
  const float* w_in = (const float*)d_in[1];
  const float* gin  = (const float*)d_in[2];
  const float* bin  = (const float*)d_in[3];
  const float* wdw  = (const float*)d_in[4];
  const float* gcv  = (const float*)d_in[5];
  const float* bcv  = (const float*)d_in[6];
  const float* wB   = (const float*)d_in[7];
  const float* wC   = (const float*)d_in[8];
  const float* A    = (const float*)d_in[9];
  const float* Dv   = (const float*)d_in[10];
  const float* wg   = (const float*)d_in[11];
  const float* gg   = (const float*)d_in[12];
  const float* bg   = (const float*)d_in[13];
  const float* wo   = (const float*)d_in[14];
  const float* go   = (const float*)d_in[15];
  const float* bo   = (const float*)d_in[16];
  float* out = (float*)d_out;

  const int SM1 = 81920 + 1024;
  const int SM4 = 114688 + 1024;
  cudaFuncSetAttribute(k_inproj, cudaFuncAttributeMaxDynamicSharedMemorySize, SM1);
  cudaFuncSetAttribute(k_final,  cudaFuncAttributeMaxDynamicSharedMemorySize, SM4);

  k_prep  <<<1, 256>>>(w_in, wg, wo);
  k_inproj<<<dim3(LL/256, BATCH), 256, SM1>>>(x, gin, bin);
  k_dwconv<<<dim3(HH/16, CH, BATCH), 128>>>(wdw, gcv, bcv);
  k_bproj <<<dim3(CUT/128, BATCH), 128>>>(wB);
  k_scan  <<<BATCH*DSTATE, 256>>>(A);
  k_final <<<dim3(LL/256, BATCH), 256, SM4>>>(wC, Dv, gg, bg, go, bo, out);
}

// round 7
// speedup vs baseline: 1.2909x; 1.2909x over previous
#include <cuda_runtime.h>
#include <cuda_bf16.h>
#include <math.h>
#include <stdint.h>

#define BATCH 8
#define CH 64
#define HH 512
#define WW 512
#define LL (HH*WW)
#define DSTATE 16
#define CUT 2048
#define BN_EPS 1e-5f

// scratch
__device__ float g_xp[(size_t)BATCH*CH*LL];
__device__ float g_xc[(size_t)BATCH*CH*LL];
__device__ float g_Bp[BATCH*DSTATE*CUT];
__device__ float g_Sp[BATCH*DSTATE*CUT];
__device__ float g_S [BATCH*DSTATE];

// pre-swizzled bf16 hi/lo weight tiles
__device__ __align__(16) unsigned char g_WinH[8192],  g_WinL[8192];
__device__ __align__(16) unsigned char g_WgH[16384],  g_WgL[16384];
__device__ __align__(16) unsigned char g_WoH[8192],   g_WoL[8192];

__device__ __forceinline__ float fsig(float x){ return 1.0f/(1.0f+__expf(-x)); }
__device__ __forceinline__ float ftanh(float x){
  x = fminf(fmaxf(x, -15.f), 15.f);
  float e = __expf(2.f*x);
  return __fdividef(e-1.f, e+1.f);
}

#define SW128(o) ((o) ^ (((o)>>3)&0x70))

__device__ __forceinline__ uint32_t smem_u32(const void* p){
  uint32_t a;
  asm("{ .reg .u64 t; cvta.to.shared.u64 t, %1; cvt.u32.u64 %0, t; }"
      : "=r"(a) : "l"(p));
  return a;
}
__device__ __forceinline__ void ldsm4(unsigned r[4], uint32_t a){
  asm volatile("ldmatrix.sync.aligned.m8n8.x4.shared.b16 {%0,%1,%2,%3}, [%4];"
    : "=r"(r[0]),"=r"(r[1]),"=r"(r[2]),"=r"(r[3]) : "r"(a));
}
__device__ __forceinline__ void mma16816(float d[4], const unsigned a[4], const unsigned b0, const unsigned b1){
  asm volatile("mma.sync.aligned.m16n8k16.row.col.f32.bf16.bf16.f32 "
    "{%0,%1,%2,%3}, {%4,%5,%6,%7}, {%8,%9}, {%0,%1,%2,%3};"
    : "+f"(d[0]),"+f"(d[1]),"+f"(d[2]),"+f"(d[3])
    : "r"(a[0]),"r"(a[1]),"r"(a[2]),"r"(a[3]), "r"(b0),"r"(b1));
}

// fast truncation split: hi = top-16-bit truncation, lo = rn(exact residual)
__device__ __forceinline__ void split2t(float v0, float v1, unsigned& hi, unsigned& lo){
  unsigned u0 = __float_as_uint(v0), u1 = __float_as_uint(v1);
  unsigned h;
  asm("prmt.b32 %0, %1, %2, 0x7632;" : "=r"(h) : "r"(u0), "r"(u1));
  float r0 = v0 - __uint_as_float(u0 & 0xFFFF0000u);
  float r1 = v1 - __uint_as_float(u1 & 0xFFFF0000u);
  unsigned l;
  asm("cvt.rn.bf16x2.f32 %0, %1, %2;" : "=r"(l) : "f"(r1), "f"(r0));
  hi = h; lo = l;
}

// ---------------------------------------------------------------------------
// K0: one-time weight prep
// ---------------------------------------------------------------------------
__global__ void k_prep(const float* __restrict__ w_in,
                       const float* __restrict__ wg,
                       const float* __restrict__ wo)
{
  const int tid = threadIdx.x;
  for (int idx=tid; idx<4096; idx+=256){
    int n = idx>>6, k = idx&63;
    unsigned off = SW128((unsigned)(n*128 + k*2));
    { float v = w_in[idx];
      float h = __bfloat162float(__float2bfloat16_rn(v));
      *(__nv_bfloat16*)(g_WinH+off) = __float2bfloat16_rn(v);
      *(__nv_bfloat16*)(g_WinL+off) = __float2bfloat16_rn(v-h); }
    { float v = wo[idx];
      float h = __bfloat162float(__float2bfloat16_rn(v));
      *(__nv_bfloat16*)(g_WoH+off) = __float2bfloat16_rn(v);
      *(__nv_bfloat16*)(g_WoL+off) = __float2bfloat16_rn(v-h); }
  }
  for (int idx=tid; idx<8192; idx+=256){
    int n = idx>>6, k = idx&63;
    unsigned off = SW128((unsigned)(n*128 + k*2));
    float v = wg[idx];
    float h = __bfloat162float(__float2bfloat16_rn(v));
    *(__nv_bfloat16*)(g_WgH+off) = __float2bfloat16_rn(v);
    *(__nv_bfloat16*)(g_WgL+off) = __float2bfloat16_rn(v-h);
  }
}

// ---------------------------------------------------------------------------
// K1: xp = silu(bn(w_in @ x)) — mma.sync bf16-split. 256 px/block, 256 thr.
// B loads via ldsm4 n-tile pairs.
// ---------------------------------------------------------------------------
__global__ __launch_bounds__(256,2) void k_inproj(
    const float* __restrict__ x,
    const float* __restrict__ gin, const float* __restrict__ bin)
{
  extern __shared__ char dynraw[];
  char* base = (char*)(((uintptr_t)dynraw + 1023) & ~(uintptr_t)1023);
  char* Ahi = base;            // 32KB
  char* Alo = base + 32768;    // 32KB
  char* Whi = base + 65536;    // 8KB
  char* Wlo = base + 73728;    // 8KB
  __shared__ float sg[64], sb[64];

  const int tid = threadIdx.x, lane = tid&31, warp = tid>>5;
  const int b = blockIdx.y;
  const long p0 = (long)blockIdx.x*256;

  for (int idx=tid; idx<512; idx+=256){
    ((uint4*)Whi)[idx] = ((const uint4*)g_WinH)[idx];
    ((uint4*)Wlo)[idx] = ((const uint4*)g_WinL)[idx];
  }
  if (tid<64){ sg[tid]=gin[tid]*rsqrtf(1.f+BN_EPS); sb[tid]=bin[tid]; }

  { // A staging
    const float* xb = x + (long)b*CH*LL + p0 + tid;
    #pragma unroll
    for (int kb=0;kb<8;kb++){
      unsigned h[4], l[4];
      #pragma unroll
      for (int j=0;j<4;j++)
        split2t(xb[(long)(8*kb+2*j)*LL], xb[(long)(8*kb+2*j+1)*LL], h[j], l[j]);
      unsigned off = SW128((unsigned)(tid*128 + kb*16));
      *(uint4*)(Ahi+off) = make_uint4(h[0],h[1],h[2],h[3]);
      *(uint4*)(Alo+off) = make_uint4(l[0],l[1],l[2],l[3]);
    }
  }
  __syncthreads();

  const uint32_t AhiB=smem_u32(Ahi), AloB=smem_u32(Alo),
                 WhiB=smem_u32(Whi), WloB=smem_u32(Wlo);
  float acc[2][8][4];
  #pragma unroll
  for (int mt=0;mt<2;mt++)
    #pragma unroll
    for (int nt=0;nt<8;nt++)
      #pragma unroll
      for (int r=0;r<4;r++) acc[mt][nt][r]=0.f;

  const int Mb = warp*32;
  const int arow = (lane&7) + ((lane>>3)&1)*8;
  const int achk = lane>>4;
  const int brow = (lane&7) + ((lane>>4)&1)*8;   // bsel folded in
  const int bchk = (lane>>3)&1;

  #pragma unroll
  for (int ks=0; ks<4; ks++){
    unsigned ah[2][4], al[2][4];
    #pragma unroll
    for (int mt=0; mt<2; mt++){
      unsigned off = SW128((unsigned)((Mb+16*mt+arow)*128 + (2*ks+achk)*16));
      ldsm4(ah[mt], AhiB+off);
      ldsm4(al[mt], AloB+off);
    }
    #pragma unroll
    for (int ntp=0; ntp<4; ntp++){
      unsigned boff = SW128((unsigned)((16*ntp+brow)*128 + (2*ks+bchk)*16));
      unsigned bh[4], bl[4];
      ldsm4(bh, WhiB+boff);
      ldsm4(bl, WloB+boff);
      #pragma unroll
      for (int mt=0;mt<2;mt++){
        mma16816(acc[mt][2*ntp],   ah[mt], bh[0], bh[1]);
        mma16816(acc[mt][2*ntp],   al[mt], bh[0], bh[1]);
        mma16816(acc[mt][2*ntp],   ah[mt], bl[0], bl[1]);
        mma16816(acc[mt][2*ntp+1], ah[mt], bh[2], bh[3]);
        mma16816(acc[mt][2*ntp+1], al[mt], bh[2], bh[3]);
        mma16816(acc[mt][2*ntp+1], ah[mt], bl[2], bl[3]);
      }
    }
  }
  __syncthreads();

  float* so = (float*)base;   // [64][268]
  #pragma unroll
  for (int mt=0;mt<2;mt++){
    int m = Mb + 16*mt + (lane>>2);
    #pragma unroll
    for (int nt=0;nt<8;nt++){
      int n = 8*nt + 2*(lane&3);
      so[n*268 + m]        = acc[mt][nt][0];
      so[(n+1)*268 + m]    = acc[mt][nt][1];
      so[n*268 + m + 8]    = acc[mt][nt][2];
      so[(n+1)*268 + m + 8]= acc[mt][nt][3];
    }
  }
  __syncthreads();

  float* dst = g_xp + (long)b*CH*LL + p0;
  #pragma unroll
  for (int r=0;r<16;r++){
    int f4 = tid + r*256;
    int ch = f4>>6, px = (f4&63)<<2;
    float4 v = *(float4*)(so + ch*268 + px);
    float sc = sg[ch], be = sb[ch];
    v.x = fmaf(v.x,sc,be); v.y = fmaf(v.y,sc,be);
    v.z = fmaf(v.z,sc,be); v.w = fmaf(v.w,sc,be);
    float4 o = make_float4(v.x*fsig(v.x), v.y*fsig(v.y), v.z*fsig(v.z), v.w*fsig(v.w));
    *(float4*)(dst + (long)ch*LL + px) = o;
  }
}

// ---------------------------------------------------------------------------
// K2: depthwise 3x3 + BN + SiLU
// ---------------------------------------------------------------------------
__global__ __launch_bounds__(128) void k_dwconv(
    const float* __restrict__ wdw, const float* __restrict__ gcv,
    const float* __restrict__ bcv)
{
  __shared__ float s[18*512];
  const int tid = threadIdx.x;
  const int b = blockIdx.z, c = blockIdx.y, h0 = blockIdx.x*16;
  const float* xpc = g_xp + (long)(b*CH+c)*LL;

  #pragma unroll
  for (int r=0;r<18;r++){
    int hh = h0 - 1 + r;
    float4 v = make_float4(0.f,0.f,0.f,0.f);
    if (hh >= 0 && hh < HH) v = *(const float4*)(xpc + (long)hh*WW + (tid<<2));
    *(float4*)(s + r*512 + (tid<<2)) = v;
  }
  __syncthreads();

  const float k0=wdw[c*9+0], k1=wdw[c*9+1], k2=wdw[c*9+2],
              k3=wdw[c*9+3], k4=wdw[c*9+4], k5=wdw[c*9+5],
              k6=wdw[c*9+6], k7=wdw[c*9+7], k8=wdw[c*9+8];
  const float rs = rsqrtf(1.0f+BN_EPS);
  const float sc = gcv[c]*rs, be = bcv[c];
  const int w = tid<<2;
  float* dst = g_xc + (long)(b*CH+c)*LL + (long)h0*WW + w;

  for (int r=0;r<16;r++){
    float in[3][6];
    #pragma unroll
    for (int dy=0;dy<3;dy++){
      const float* row = s + (r+dy)*512;
      in[dy][0] = (w>0)? row[w-1] : 0.f;
      float4 m = *(const float4*)(row + w);
      in[dy][1]=m.x; in[dy][2]=m.y; in[dy][3]=m.z; in[dy][4]=m.w;
      in[dy][5] = (w<508)? row[w+4] : 0.f;
    }
    float o[4];
    #pragma unroll
    for (int j=0;j<4;j++){
      float a = k0*in[0][j] + k1*in[0][j+1] + k2*in[0][j+2]
              + k3*in[1][j] + k4*in[1][j+1] + k5*in[1][j+2]
              + k6*in[2][j] + k7*in[2][j+1] + k8*in[2][j+2];
      a = fmaf(a, sc, be);
      o[j] = a*fsig(a);
    }
    *(float4*)(dst + (long)r*WW) = make_float4(o[0],o[1],o[2],o[3]);
  }
}

// ---------------------------------------------------------------------------
// K3a: Bp = wB @ xc for k < CUT.  64 px/block x 4 channel groups, smem reduce.
// ---------------------------------------------------------------------------
__global__ __launch_bounds__(256) void k_bproj(const float* __restrict__ wB)
{
  __shared__ float swB[DSTATE*64];
  __shared__ float red[256][17];
  const int tid = threadIdx.x;
  const int b = blockIdx.y;
  const int px = tid & 63, cg = tid >> 6;
  const int k = blockIdx.x*64 + px;

  for (int idx=tid; idx<DSTATE*64; idx+=256) swB[idx] = wB[idx];
  __syncthreads();

  const float* xcb = g_xc + (long)b*CH*LL + k;
  float acc[16];
  #pragma unroll
  for (int s=0;s<16;s++) acc[s]=0.f;
  #pragma unroll
  for (int i=0;i<16;i++){
    int ch = cg*16 + i;
    float xv = xcb[(long)ch*LL];
    #pragma unroll
    for (int s=0;s<16;s++) acc[s] = fmaf(swB[s*64+ch], xv, acc[s]);
  }
  #pragma unroll
  for (int s=0;s<16;s++) red[tid][s] = acc[s];
  __syncthreads();
  if (cg == 0){
    #pragma unroll
    for (int s=0;s<16;s++){
      float v = red[px][s] + red[64+px][s] + red[128+px][s] + red[192+px][s];
      g_Bp[(b*DSTATE+s)*CUT + k] = v;
    }
  }
}

__global__ __launch_bounds__(256) void k_scan(const float* __restrict__ A)
{
  __shared__ float t[CUT];
  const int bs = blockIdx.x;
  const int s = bs & 15;
  const float a = A[s];
  for (int idx = threadIdx.x; idx < CUT; idx += 256)
    t[idx] = g_Bp[bs*CUT + idx] * expf(a * (float)idx);
  __syncthreads();
  if (threadIdx.x == 0){
    float acc = 0.f;
    for (int k=0;k<CUT;k++){ acc += t[k]; t[k] = acc; }
    g_S[bs] = acc;
  }
  __syncthreads();
  for (int idx = threadIdx.x; idx < CUT; idx += 256)
    g_Sp[bs*CUT + idx] = t[idx];
}

// ---------------------------------------------------------------------------
// K4: gate GEMM + combine + out GEMM. 128 px/block, 256 thr, 2 blocks/SM.
// B loads via ldsm4 n-tile pairs; cvec folded in.
// ---------------------------------------------------------------------------
__global__ __launch_bounds__(256,2) void k_final(
  const float* __restrict__ wC, const float* __restrict__ Dv,
  const float* __restrict__ gg, const float* __restrict__ bg,
  const float* __restrict__ go, const float* __restrict__ bo,
  float* __restrict__ out)
{
  extern __shared__ char dynraw[];
  char* base = (char*)(((uintptr_t)dynraw + 1023) & ~(uintptr_t)1023);
  char* Ahi  = base;            // 16KB (xp, later xg)
  char* Alo  = base + 16384;    // 16KB
  char* WgHi = base + 32768;    // 16KB
  char* WgLo = base + 49152;    // 16KB
  char* WoHi = base + 65536;    // 8KB
  char* WoLo = base + 73728;    // 8KB  (total 80KB)
  __shared__ float s_gsc[128], s_gbe[128], s_dvec[64], s_cvec[64], s_osc[64], s_obe[64];
  __shared__ float s_wC[64*16];

  const int tid = threadIdx.x, lane = tid&31, warp = tid>>5;
  const int b = blockIdx.y;
  const long p0 = (long)blockIdx.x*128;
  const bool boundary = (p0 < CUT);
  const float rs = rsqrtf(1.0f+BN_EPS);

  for (int idx=tid; idx<1024; idx+=256){
    ((uint4*)WgHi)[idx] = ((const uint4*)g_WgH)[idx];
    ((uint4*)WgLo)[idx] = ((const uint4*)g_WgL)[idx];
  }
  for (int idx=tid; idx<512; idx+=256){
    ((uint4*)WoHi)[idx] = ((const uint4*)g_WoH)[idx];
    ((uint4*)WoLo)[idx] = ((const uint4*)g_WoL)[idx];
  }
  if (tid < 128){ s_gsc[tid] = gg[tid]*rs; s_gbe[tid] = bg[tid]; }
  for (int idx=tid; idx<1024; idx+=256) s_wC[idx] = wC[idx];
  if (tid < 64){
    s_dvec[tid] = Dv[tid];
    s_osc[tid]  = go[tid]*rs;
    s_obe[tid]  = bo[tid];
    float c = 0.f;
    #pragma unroll
    for (int s=0;s<16;s++) c = fmaf(wC[tid*16+s], g_S[b*16+s], c);
    s_cvec[tid] = c;
  }

  { // A staging: thread = (px = tid&127, channel half = tid>>7)
    const int px = tid & 127, half = tid >> 7;
    const float* xpb = g_xp + (long)b*CH*LL + (long)(half*32)*LL + p0 + px;
    #pragma unroll
    for (int j=0;j<4;j++){
      unsigned h[4], l[4];
      #pragma unroll
      for (int c=0;c<4;c++)
        split2t(xpb[(long)(8*j+2*c)*LL], xpb[(long)(8*j+2*c+1)*LL], h[c], l[c]);
      unsigned off = SW128((unsigned)(px*128 + (half*4+j)*16));
      *(uint4*)(Ahi+off) = make_uint4(h[0],h[1],h[2],h[3]);
      *(uint4*)(Alo+off) = make_uint4(l[0],l[1],l[2],l[3]);
    }
  }
  __syncthreads();

  const uint32_t AhiB=smem_u32(Ahi), AloB=smem_u32(Alo),
                 WgHiB=smem_u32(WgHi), WgLoB=smem_u32(WgLo),
                 WoHiB=smem_u32(WoHi), WoLoB=smem_u32(WoLo);
  const int Mb = warp*16;
  const int arow = (lane&7) + ((lane>>3)&1)*8;
  const int achk = lane>>4;
  const int brow = (lane&7) + ((lane>>4)&1)*8;
  const int bchk = (lane>>3)&1;

  // preload A fragments (xp): 32 regs
  unsigned ah[4][4], al[4][4];
  #pragma unroll
  for (int ks=0; ks<4; ks++){
    unsigned aoff = SW128((unsigned)((Mb+arow)*128 + (2*ks+achk)*16));
    ldsm4(ah[ks], AhiB+aoff);
    ldsm4(al[ks], AloB+aoff);
  }

  // gate GEMM + combine, streamed per nt pair
  const float* xcb = g_xc + (long)b*CH*LL + p0;
  #pragma unroll
  for (int ntp=0; ntp<4; ntp++){
    float accg[2][4] = {{0.f,0.f,0.f,0.f},{0.f,0.f,0.f,0.f}};
    float accs[2][4] = {{0.f,0.f,0.f,0.f},{0.f,0.f,0.f,0.f}};
    #pragma unroll
    for (int ks=0; ks<4; ks++){
      unsigned bgo = SW128((unsigned)((16*ntp+brow)*128 + (2*ks+bchk)*16));
      unsigned bso = SW128((unsigned)((16*ntp+64+brow)*128 + (2*ks+bchk)*16));
      unsigned bh[4], bl[4];
      ldsm4(bh, WgHiB+bgo); ldsm4(bl, WgLoB+bgo);
      mma16816(accg[0], ah[ks], bh[0], bh[1]);
      mma16816(accg[0], al[ks], bh[0], bh[1]);
      mma16816(accg[0], ah[ks], bl[0], bl[1]);
      mma16816(accg[1], ah[ks], bh[2], bh[3]);
      mma16816(accg[1], al[ks], bh[2], bh[3]);
      mma16816(accg[1], ah[ks], bl[2], bl[3]);
      ldsm4(bh, WgHiB+bso); ldsm4(bl, WgLoB+bso);
      mma16816(accs[0], ah[ks], bh[0], bh[1]);
      mma16816(accs[0], al[ks], bh[0], bh[1]);
      mma16816(accs[0], ah[ks], bl[0], bl[1]);
      mma16816(accs[1], ah[ks], bh[2], bh[3]);
      mma16816(accs[1], al[ks], bh[2], bh[3]);
      mma16816(accs[1], ah[ks], bl[2], bl[3]);
    }
    #pragma unroll
    for (int sub=0; sub<2; sub++){
      const int nt = 2*ntp + sub;
      const int ch0 = 8*nt + 2*(lane&3), ch1 = ch0+1;
      const float dv0 = s_dvec[ch0], dv1 = s_dvec[ch1];
      #pragma unroll
      for (int rp=0; rp<2; rp++){
        const int pxl = Mb + (lane>>2) + rp*8;
        float base0, base1;
        if (boundary){
          const long p = p0 + pxl;
          float d0=0.f, d1=0.f;
          for (int s=0;s<16;s++){
            float sv = g_Sp[(b*DSTATE+s)*CUT + p];
            d0 = fmaf(s_wC[ch0*16+s], sv, d0);
            d1 = fmaf(s_wC[ch1*16+s], sv, d1);
          }
          base0=d0; base1=d1;
        } else { base0 = s_cvec[ch0]; base1 = s_cvec[ch1]; }
        float xc0 = xcb[(long)ch0*LL + pxl];
        float xc1 = xcb[(long)ch1*LL + pxl];
        float g0 = fmaf(accg[sub][2*rp],   s_gsc[ch0], s_gbe[ch0]);
        float g1 = fmaf(accg[sub][2*rp+1], s_gsc[ch1], s_gbe[ch1]);
        float h0 = fmaf(accs[sub][2*rp],   s_gsc[64+ch0], s_gbe[64+ch0]);
        float h1 = fmaf(accs[sub][2*rp+1], s_gsc[64+ch1], s_gbe[64+ch1]);
        float v0 = fsig(g0)*(fmaf(dv0, xc0, base0) + ftanh(h0));
        float v1 = fsig(g1)*(fmaf(dv1, xc1, base1) + ftanh(h1));
        unsigned hi, lo;
        split2t(v0, v1, hi, lo);
        unsigned off = SW128((unsigned)(pxl*128 + ch0*2));
        *(unsigned*)(Ahi+off) = hi;
        *(unsigned*)(Alo+off) = lo;
      }
    }
  }
  __syncwarp();   // rows [Mb, Mb+16) are warp-private

  // reload A fragments (xg)
  #pragma unroll
  for (int ks=0; ks<4; ks++){
    unsigned aoff = SW128((unsigned)((Mb+arow)*128 + (2*ks+achk)*16));
    ldsm4(ah[ks], AhiB+aoff);
    ldsm4(al[ks], AloB+aoff);
  }
  // out GEMM
  float acc2[8][4];
  #pragma unroll
  for (int nt=0;nt<8;nt++)
    #pragma unroll
    for (int r=0;r<4;r++) acc2[nt][r]=0.f;
  #pragma unroll
  for (int ks=0; ks<4; ks++){
    #pragma unroll
    for (int ntp=0; ntp<4; ntp++){
      unsigned boff = SW128((unsigned)((16*ntp+brow)*128 + (2*ks+bchk)*16));
      unsigned bh[4], bl[4];
      ldsm4(bh, WoHiB+boff);
      ldsm4(bl, WoLoB+boff);
      mma16816(acc2[2*ntp],   ah[ks], bh[0], bh[1]);
      mma16816(acc2[2*ntp],   al[ks], bh[0], bh[1]);
      mma16816(acc2[2*ntp],   ah[ks], bl[0], bl[1]);
      mma16816(acc2[2*ntp+1], ah[ks], bh[2], bh[3]);
      mma16816(acc2[2*ntp+1], al[ks], bh[2], bh[3]);
      mma16816(acc2[2*ntp+1], ah[ks], bl[2], bl[3]);
    }
  }
  __syncthreads();

  float* so = (float*)(base + 32768);   // [64][132] over WgHi/WgLo (dead)
  {
    int m = Mb + (lane>>2);
    #pragma unroll
    for (int nt=0;nt<8;nt++){
      int n = 8*nt + 2*(lane&3);
      so[n*132 + m]        = acc2[nt][0];
      so[(n+1)*132 + m]    = acc2[nt][1];
      so[n*132 + m + 8]    = acc2[nt][2];
      so[(n+1)*132 + m + 8]= acc2[nt][3];
    }
  }
  __syncthreads();

  float* dst = out + (long)b*CH*LL + p0;
  #pragma unroll
  for (int r=0;r<8;r++){
    int f4 = tid + r*256;
    int ch = f4>>5, px = (f4&31)<<2;
    float4 v = *(float4*)(so + ch*132 + px);
    float sc = s_osc[ch], be = s_obe[ch];
    float4 o = make_float4(fmaf(v.x,sc,be), fmaf(v.y,sc,be),
                           fmaf(v.z,sc,be), fmaf(v.w,sc,be));
    *(float4*)(dst + (long)ch*LL + px) = o;
  }
}

// ---------------------------------------------------------------------------
extern "C" void kernel_launch(void* const* d_in, const int* in_sizes, int n_in,
                              void* d_out, int out_size)
{
  const float* x    = (const float*)d_in[0];
  const float* w_in = (const float*)d_in[1];
  const float* gin  = (const float*)d_in[2];
  const float* bin  = (const float*)d_in[3];
  const float* wdw  = (const float*)d_in[4];
  const float* gcv  = (const float*)d_in[5];
  const float* bcv  = (const float*)d_in[6];
  const float* wB   = (const float*)d_in[7];
  const float* wC   = (const float*)d_in[8];
  const float* A    = (const float*)d_in[9];
  const float* Dv   = (const float*)d_in[10];
  const float* wg   = (const float*)d_in[11];
  const float* gg   = (const float*)d_in[12];
  const float* bg   = (const float*)d_in[13];
  const float* wo   = (const float*)d_in[14];
  const float* go   = (const float*)d_in[15];
  const float* bo   = (const float*)d_in[16];
  float* out = (float*)d_out;

  const int SM1 = 81920 + 1024;
  const int SM4 = 81920 + 1024;
  cudaFuncSetAttribute(k_inproj, cudaFuncAttributeMaxDynamicSharedMemorySize, SM1);
  cudaFuncSetAttribute(k_final,  cudaFuncAttributeMaxDynamicSharedMemorySize, SM4);

  k_prep  <<<1, 256>>>(w_in, wg, wo);
  k_inproj<<<dim3(LL/256, BATCH), 256, SM1>>>(x, gin, bin);
  k_dwconv<<<dim3(HH/16, CH, BATCH), 128>>>(wdw, gcv, bcv);
  k_bproj <<<dim3(CUT/64, BATCH), 256>>>(wB);
  k_scan  <<<BATCH*DSTATE, 256>>>(A);
  k_final <<<dim3(LL/128, BATCH), 256, SM4>>>(wC, Dv, gg, bg, go, bo, out);
}

// round 8
// speedup vs baseline: 1.4326x; 1.1098x over previous
#include <cuda_runtime.h>
#include <cuda_fp16.h>
#include <math.h>
#include <stdint.h>

#define BATCH 8
#define CH 64
#define HH 512
#define WW 512
#define LL (HH*WW)
#define DSTATE 16
#define CUT 2048
#define BN_EPS 1e-5f

// scratch
__device__ float g_xp[(size_t)BATCH*CH*LL];
__device__ float g_xc[(size_t)BATCH*CH*LL];
__device__ float g_Bp[BATCH*DSTATE*CUT];
__device__ float g_Sp[BATCH*DSTATE*CUT];
__device__ float g_S [BATCH*DSTATE];

// pre-swizzled fp16 weight tiles (single precision pass for B)
__device__ __align__(16) unsigned char g_Win[8192];
__device__ __align__(16) unsigned char g_Wg [16384];
__device__ __align__(16) unsigned char g_Wo [8192];

__device__ __forceinline__ float fsig(float x){ return 1.0f/(1.0f+__expf(-x)); }
__device__ __forceinline__ float ftanh(float x){
  x = fminf(fmaxf(x, -15.f), 15.f);
  float e = __expf(2.f*x);
  return __fdividef(e-1.f, e+1.f);
}

#define SW128(o) ((o) ^ (((o)>>3)&0x70))

__device__ __forceinline__ uint32_t smem_u32(const void* p){
  uint32_t a;
  asm("{ .reg .u64 t; cvta.to.shared.u64 t, %1; cvt.u32.u64 %0, t; }"
      : "=r"(a) : "l"(p));
  return a;
}
__device__ __forceinline__ void ldsm4(unsigned r[4], uint32_t a){
  asm volatile("ldmatrix.sync.aligned.m8n8.x4.shared.b16 {%0,%1,%2,%3}, [%4];"
    : "=r"(r[0]),"=r"(r[1]),"=r"(r[2]),"=r"(r[3]) : "r"(a));
}
__device__ __forceinline__ void ldsm2(unsigned r[2], uint32_t a){
  asm volatile("ldmatrix.sync.aligned.m8n8.x2.shared.b16 {%0,%1}, [%2];"
    : "=r"(r[0]),"=r"(r[1]) : "r"(a));
}
__device__ __forceinline__ void mmah(float d[4], const unsigned a[4], const unsigned b0, const unsigned b1){
  asm volatile("mma.sync.aligned.m16n8k16.row.col.f32.f16.f16.f32 "
    "{%0,%1,%2,%3}, {%4,%5,%6,%7}, {%8,%9}, {%0,%1,%2,%3};"
    : "+f"(d[0]),"+f"(d[1]),"+f"(d[2]),"+f"(d[3])
    : "r"(a[0]),"r"(a[1]),"r"(a[2]),"r"(a[3]), "r"(b0),"r"(b1));
}

// fp16 split: hi = rn(v), lo = rn(v - hi)   (packed pairs, lo half = even elem)
__device__ __forceinline__ void split2h(float v0, float v1, unsigned& hi, unsigned& lo){
  __half2 hh = __floats2half2_rn(v0, v1);
  hi = *(unsigned*)&hh;
  float r0 = v0 - __half2float(__low2half(hh));
  float r1 = v1 - __half2float(__high2half(hh));
  __half2 ll = __floats2half2_rn(r0, r1);
  lo = *(unsigned*)&ll;
}

// ---------------------------------------------------------------------------
// K0: one-time weight prep (fp16, SW128-swizzled 128B rows)
// ---------------------------------------------------------------------------
__global__ void k_prep(const float* __restrict__ w_in,
                       const float* __restrict__ wg,
                       const float* __restrict__ wo)
{
  const int tid = threadIdx.x;
  for (int idx=tid; idx<4096; idx+=256){
    int n = idx>>6, k = idx&63;
    unsigned off = SW128((unsigned)(n*128 + k*2));
    *(__half*)(g_Win+off) = __float2half_rn(w_in[idx]);
    *(__half*)(g_Wo +off) = __float2half_rn(wo[idx]);
  }
  for (int idx=tid; idx<8192; idx+=256){
    int n = idx>>6, k = idx&63;
    unsigned off = SW128((unsigned)(n*128 + k*2));
    *(__half*)(g_Wg+off) = __float2half_rn(wg[idx]);
  }
}

// ---------------------------------------------------------------------------
// K1: xp = silu(bn(w_in @ x)) — fp16 2-pass mma. 256 px/block, 256 thr.
// ---------------------------------------------------------------------------
__global__ __launch_bounds__(256,2) void k_inproj(
    const float* __restrict__ x,
    const float* __restrict__ gin, const float* __restrict__ bin)
{
  extern __shared__ char dynraw[];
  char* base = (char*)(((uintptr_t)dynraw + 1023) & ~(uintptr_t)1023);
  char* Ahi = base;            // 32KB
  char* Alo = base + 32768;    // 32KB
  char* Wt  = base + 65536;    // 8KB
  __shared__ float sg[64], sb[64];

  const int tid = threadIdx.x, lane = tid&31, warp = tid>>5;
  const int b = blockIdx.y;
  const long p0 = (long)blockIdx.x*256;

  for (int idx=tid; idx<512; idx+=256)
    ((uint4*)Wt)[idx] = ((const uint4*)g_Win)[idx];
  if (tid<64){ sg[tid]=gin[tid]*rsqrtf(1.f+BN_EPS); sb[tid]=bin[tid]; }

  { // A staging: thread = pixel
    const float* xb = x + (long)b*CH*LL + p0 + tid;
    #pragma unroll
    for (int kb=0;kb<8;kb++){
      unsigned h[4], l[4];
      #pragma unroll
      for (int j=0;j<4;j++)
        split2h(xb[(long)(8*kb+2*j)*LL], xb[(long)(8*kb+2*j+1)*LL], h[j], l[j]);
      unsigned off = SW128((unsigned)(tid*128 + kb*16));
      *(uint4*)(Ahi+off) = make_uint4(h[0],h[1],h[2],h[3]);
      *(uint4*)(Alo+off) = make_uint4(l[0],l[1],l[2],l[3]);
    }
  }
  __syncthreads();

  const uint32_t AhiB=smem_u32(Ahi), AloB=smem_u32(Alo), WtB=smem_u32(Wt);
  float acc[2][8][4];
  #pragma unroll
  for (int mt=0;mt<2;mt++)
    #pragma unroll
    for (int nt=0;nt<8;nt++)
      #pragma unroll
      for (int r=0;r<4;r++) acc[mt][nt][r]=0.f;

  const int Mb = warp*32;
  const int arow = (lane&7) + ((lane>>3)&1)*8;
  const int achk = lane>>4;
  const int brow = lane&7;
  const int bchk = (lane>>3)&1;

  #pragma unroll
  for (int ks=0; ks<4; ks++){
    unsigned ah[2][4], al[2][4];
    #pragma unroll
    for (int mt=0; mt<2; mt++){
      unsigned off = SW128((unsigned)((Mb+16*mt+arow)*128 + (2*ks+achk)*16));
      ldsm4(ah[mt], AhiB+off);
      ldsm4(al[mt], AloB+off);
    }
    #pragma unroll
    for (int nt=0; nt<8; nt++){
      unsigned boff = SW128((unsigned)((8*nt+brow)*128 + (2*ks+bchk)*16));
      unsigned bw[2];
      ldsm2(bw, WtB+boff);
      #pragma unroll
      for (int mt=0;mt<2;mt++){
        mmah(acc[mt][nt], ah[mt], bw[0], bw[1]);
        mmah(acc[mt][nt], al[mt], bw[0], bw[1]);
      }
    }
  }
  __syncthreads();

  float* so = (float*)base;   // [64][268]
  #pragma unroll
  for (int mt=0;mt<2;mt++){
    int m = Mb + 16*mt + (lane>>2);
    #pragma unroll
    for (int nt=0;nt<8;nt++){
      int n = 8*nt + 2*(lane&3);
      so[n*268 + m]        = acc[mt][nt][0];
      so[(n+1)*268 + m]    = acc[mt][nt][1];
      so[n*268 + m + 8]    = acc[mt][nt][2];
      so[(n+1)*268 + m + 8]= acc[mt][nt][3];
    }
  }
  __syncthreads();

  float* dst = g_xp + (long)b*CH*LL + p0;
  #pragma unroll
  for (int r=0;r<16;r++){
    int f4 = tid + r*256;
    int ch = f4>>6, px = (f4&63)<<2;
    float4 v = *(float4*)(so + ch*268 + px);
    float sc = sg[ch], be = sb[ch];
    v.x = fmaf(v.x,sc,be); v.y = fmaf(v.y,sc,be);
    v.z = fmaf(v.z,sc,be); v.w = fmaf(v.w,sc,be);
    float4 o = make_float4(v.x*fsig(v.x), v.y*fsig(v.y), v.z*fsig(v.z), v.w*fsig(v.w));
    *(float4*)(dst + (long)ch*LL + px) = o;
  }
}

// ---------------------------------------------------------------------------
// K2: depthwise 3x3 + BN + SiLU
// ---------------------------------------------------------------------------
__global__ __launch_bounds__(128) void k_dwconv(
    const float* __restrict__ wdw, const float* __restrict__ gcv,
    const float* __restrict__ bcv)
{
  __shared__ float s[18*512];
  const int tid = threadIdx.x;
  const int b = blockIdx.z, c = blockIdx.y, h0 = blockIdx.x*16;
  const float* xpc = g_xp + (long)(b*CH+c)*LL;

  #pragma unroll
  for (int r=0;r<18;r++){
    int hh = h0 - 1 + r;
    float4 v = make_float4(0.f,0.f,0.f,0.f);
    if (hh >= 0 && hh < HH) v = *(const float4*)(xpc + (long)hh*WW + (tid<<2));
    *(float4*)(s + r*512 + (tid<<2)) = v;
  }
  __syncthreads();

  const float k0=wdw[c*9+0], k1=wdw[c*9+1], k2=wdw[c*9+2],
              k3=wdw[c*9+3], k4=wdw[c*9+4], k5=wdw[c*9+5],
              k6=wdw[c*9+6], k7=wdw[c*9+7], k8=wdw[c*9+8];
  const float rs = rsqrtf(1.0f+BN_EPS);
  const float sc = gcv[c]*rs, be = bcv[c];
  const int w = tid<<2;
  float* dst = g_xc + (long)(b*CH+c)*LL + (long)h0*WW + w;

  for (int r=0;r<16;r++){
    float in[3][6];
    #pragma unroll
    for (int dy=0;dy<3;dy++){
      const float* row = s + (r+dy)*512;
      in[dy][0] = (w>0)? row[w-1] : 0.f;
      float4 m = *(const float4*)(row + w);
      in[dy][1]=m.x; in[dy][2]=m.y; in[dy][3]=m.z; in[dy][4]=m.w;
      in[dy][5] = (w<508)? row[w+4] : 0.f;
    }
    float o[4];
    #pragma unroll
    for (int j=0;j<4;j++){
      float a = k0*in[0][j] + k1*in[0][j+1] + k2*in[0][j+2]
              + k3*in[1][j] + k4*in[1][j+1] + k5*in[1][j+2]
              + k6*in[2][j] + k7*in[2][j+1] + k8*in[2][j+2];
      a = fmaf(a, sc, be);
      o[j] = a*fsig(a);
    }
    *(float4*)(dst + (long)r*WW) = make_float4(o[0],o[1],o[2],o[3]);
  }
}

// ---------------------------------------------------------------------------
// K3a: Bp = wB @ xc for k < CUT.  64 px/block x 4 channel groups, smem reduce.
// ---------------------------------------------------------------------------
__global__ __launch_bounds__(256) void k_bproj(const float* __restrict__ wB)
{
  __shared__ float swB[DSTATE*64];
  __shared__ float red[256][17];
  const int tid = threadIdx.x;
  const int b = blockIdx.y;
  const int px = tid & 63, cg = tid >> 6;
  const int k = blockIdx.x*64 + px;

  for (int idx=tid; idx<DSTATE*64; idx+=256) swB[idx] = wB[idx];
  __syncthreads();

  const float* xcb = g_xc + (long)b*CH*LL + k;
  float acc[16];
  #pragma unroll
  for (int s=0;s<16;s++) acc[s]=0.f;
  #pragma unroll
  for (int i=0;i<16;i++){
    int ch = cg*16 + i;
    float xv = xcb[(long)ch*LL];
    #pragma unroll
    for (int s=0;s<16;s++) acc[s] = fmaf(swB[s*64+ch], xv, acc[s]);
  }
  #pragma unroll
  for (int s=0;s<16;s++) red[tid][s] = acc[s];
  __syncthreads();
  if (cg == 0){
    #pragma unroll
    for (int s=0;s<16;s++){
      float v = red[px][s] + red[64+px][s] + red[128+px][s] + red[192+px][s];
      g_Bp[(b*DSTATE+s)*CUT + k] = v;
    }
  }
}

__global__ __launch_bounds__(256) void k_scan(const float* __restrict__ A)
{
  __shared__ float t[CUT];
  const int bs = blockIdx.x;
  const int s = bs & 15;
  const float a = A[s];
  for (int idx = threadIdx.x; idx < CUT; idx += 256)
    t[idx] = g_Bp[bs*CUT + idx] * expf(a * (float)idx);
  __syncthreads();
  if (threadIdx.x == 0){
    float acc = 0.f;
    for (int k=0;k<CUT;k++){ acc += t[k]; t[k] = acc; }
    g_S[bs] = acc;
  }
  __syncthreads();
  for (int idx = threadIdx.x; idx < CUT; idx += 256)
    g_Sp[bs*CUT + idx] = t[idx];
}

// ---------------------------------------------------------------------------
// K4: gate GEMM + combine + out GEMM, fp16 2-pass. 128 px/block, 256 thr.
// ---------------------------------------------------------------------------
__global__ __launch_bounds__(256,2) void k_final(
  const float* __restrict__ wC, const float* __restrict__ Dv,
  const float* __restrict__ gg, const float* __restrict__ bg,
  const float* __restrict__ go, const float* __restrict__ bo,
  float* __restrict__ out)
{
  extern __shared__ char dynraw[];
  char* base = (char*)(((uintptr_t)dynraw + 1023) & ~(uintptr_t)1023);
  char* Ahi = base;            // 16KB (xp, later xg)
  char* Alo = base + 16384;    // 16KB
  char* Wg  = base + 32768;    // 16KB
  char* Wo  = base + 49152;    // 8KB   (total 56KB)
  __shared__ float s_gsc[128], s_gbe[128], s_dvec[64], s_cvec[64], s_osc[64], s_obe[64];
  __shared__ float s_wC[64*16];

  const int tid = threadIdx.x, lane = tid&31, warp = tid>>5;
  const int b = blockIdx.y;
  const long p0 = (long)blockIdx.x*128;
  const bool boundary = (p0 < CUT);
  const float rs = rsqrtf(1.0f+BN_EPS);

  for (int idx=tid; idx<1024; idx+=256)
    ((uint4*)Wg)[idx] = ((const uint4*)g_Wg)[idx];
  for (int idx=tid; idx<512; idx+=256)
    ((uint4*)Wo)[idx] = ((const uint4*)g_Wo)[idx];
  if (tid < 128){ s_gsc[tid] = gg[tid]*rs; s_gbe[tid] = bg[tid]; }
  for (int idx=tid; idx<1024; idx+=256) s_wC[idx] = wC[idx];
  if (tid < 64){
    s_dvec[tid] = Dv[tid];
    s_osc[tid]  = go[tid]*rs;
    s_obe[tid]  = bo[tid];
    float c = 0.f;
    #pragma unroll
    for (int s=0;s<16;s++) c = fmaf(wC[tid*16+s], g_S[b*16+s], c);
    s_cvec[tid] = c;
  }

  { // A staging: thread = (px = tid&127, channel half = tid>>7)
    const int px = tid & 127, half = tid >> 7;
    const float* xpb = g_xp + (long)b*CH*LL + (long)(half*32)*LL + p0 + px;
    #pragma unroll
    for (int j=0;j<4;j++){
      unsigned h[4], l[4];
      #pragma unroll
      for (int c=0;c<4;c++)
        split2h(xpb[(long)(8*j+2*c)*LL], xpb[(long)(8*j+2*c+1)*LL], h[c], l[c]);
      unsigned off = SW128((unsigned)(px*128 + (half*4+j)*16));
      *(uint4*)(Ahi+off) = make_uint4(h[0],h[1],h[2],h[3]);
      *(uint4*)(Alo+off) = make_uint4(l[0],l[1],l[2],l[3]);
    }
  }
  __syncthreads();

  const uint32_t AhiB=smem_u32(Ahi), AloB=smem_u32(Alo),
                 WgB=smem_u32(Wg), WoB=smem_u32(Wo);
  const int Mb = warp*16;
  const int arow = (lane&7) + ((lane>>3)&1)*8;
  const int achk = lane>>4;
  const int brow = lane&7;
  const int bchk = (lane>>3)&1;

  // preload A fragments (xp): 32 regs
  unsigned ah[4][4], al[4][4];
  #pragma unroll
  for (int ks=0; ks<4; ks++){
    unsigned aoff = SW128((unsigned)((Mb+arow)*128 + (2*ks+achk)*16));
    ldsm4(ah[ks], AhiB+aoff);
    ldsm4(al[ks], AloB+aoff);
  }

  // gate GEMM + combine, streamed per nt
  const float* xcb = g_xc + (long)b*CH*LL + p0;
  #pragma unroll
  for (int nt=0; nt<8; nt++){
    float accg[4] = {0.f,0.f,0.f,0.f};
    float accs[4] = {0.f,0.f,0.f,0.f};
    #pragma unroll
    for (int ks=0; ks<4; ks++){
      unsigned bgo = SW128((unsigned)((8*nt+brow)*128 + (2*ks+bchk)*16));
      unsigned bso = SW128((unsigned)((8*(nt+8)+brow)*128 + (2*ks+bchk)*16));
      unsigned bw[2];
      ldsm2(bw, WgB+bgo);
      mmah(accg, ah[ks], bw[0], bw[1]);
      mmah(accg, al[ks], bw[0], bw[1]);
      ldsm2(bw, WgB+bso);
      mmah(accs, ah[ks], bw[0], bw[1]);
      mmah(accs, al[ks], bw[0], bw[1]);
    }
    const int ch0 = 8*nt + 2*(lane&3), ch1 = ch0+1;
    const float dv0 = s_dvec[ch0], dv1 = s_dvec[ch1];
    #pragma unroll
    for (int rp=0; rp<2; rp++){
      const int pxl = Mb + (lane>>2) + rp*8;
      float base0, base1;
      if (boundary){
        const long p = p0 + pxl;
        float d0=0.f, d1=0.f;
        for (int s=0;s<16;s++){
          float sv = g_Sp[(b*DSTATE+s)*CUT + p];
          d0 = fmaf(s_wC[ch0*16+s], sv, d0);
          d1 = fmaf(s_wC[ch1*16+s], sv, d1);
        }
        base0=d0; base1=d1;
      } else { base0 = s_cvec[ch0]; base1 = s_cvec[ch1]; }
      float xc0 = xcb[(long)ch0*LL + pxl];
      float xc1 = xcb[(long)ch1*LL + pxl];
      float g0 = fmaf(accg[2*rp],   s_gsc[ch0], s_gbe[ch0]);
      float g1 = fmaf(accg[2*rp+1], s_gsc[ch1], s_gbe[ch1]);
      float h0 = fmaf(accs[2*rp],   s_gsc[64+ch0], s_gbe[64+ch0]);
      float h1 = fmaf(accs[2*rp+1], s_gsc[64+ch1], s_gbe[64+ch1]);
      float v0 = fsig(g0)*(fmaf(dv0, xc0, base0) + ftanh(h0));
      float v1 = fsig(g1)*(fmaf(dv1, xc1, base1) + ftanh(h1));
      unsigned hi, lo;
      split2h(v0, v1, hi, lo);
      unsigned off = SW128((unsigned)(pxl*128 + ch0*2));
      *(unsigned*)(Ahi+off) = hi;
      *(unsigned*)(Alo+off) = lo;
    }
  }
  __syncwarp();   // rows [Mb, Mb+16) are warp-private

  // reload A fragments (xg)
  #pragma unroll
  for (int ks=0; ks<4; ks++){
    unsigned aoff = SW128((unsigned)((Mb+arow)*128 + (2*ks+achk)*16));
    ldsm4(ah[ks], AhiB+aoff);
    ldsm4(al[ks], AloB+aoff);
  }
  // out GEMM
  float acc2[8][4];
  #pragma unroll
  for (int nt=0;nt<8;nt++)
    #pragma unroll
    for (int r=0;r<4;r++) acc2[nt][r]=0.f;
  #pragma unroll
  for (int ks=0; ks<4; ks++){
    #pragma unroll
    for (int nt=0; nt<8; nt++){
      unsigned boff = SW128((unsigned)((8*nt+brow)*128 + (2*ks+bchk)*16));
      unsigned bw[2];
      ldsm2(bw, WoB+boff);
      mmah(acc2[nt], ah[ks], bw[0], bw[1]);
      mmah(acc2[nt], al[ks], bw[0], bw[1]);
    }
  }
  __syncthreads();

  float* so = (float*)(base + 16384);   // [64][132] over Alo+Wg (dead)
  {
    int m = Mb + (lane>>2);
    #pragma unroll
    for (int nt=0;nt<8;nt++){
      int n = 8*nt + 2*(lane&3);
      so[n*132 + m]        = acc2[nt][0];
      so[(n+1)*132 + m]    = acc2[nt][1];
      so[n*132 + m + 8]    = acc2[nt][2];
      so[(n+1)*132 + m + 8]= acc2[nt][3];
    }
  }
  __syncthreads();

  float* dst = out + (long)b*CH*LL + p0;
  #pragma unroll
  for (int r=0;r<8;r++){
    int f4 = tid + r*256;
    int ch = f4>>5, px = (f4&31)<<2;
    float4 v = *(float4*)(so + ch*132 + px);
    float sc = s_osc[ch], be = s_obe[ch];
    float4 o = make_float4(fmaf(v.x,sc,be), fmaf(v.y,sc,be),
                           fmaf(v.z,sc,be), fmaf(v.w,sc,be));
    *(float4*)(dst + (long)ch*LL + px) = o;
  }
}

// ---------------------------------------------------------------------------
extern "C" void kernel_launch(void* const* d_in, const int* in_sizes, int n_in,
                              void* d_out, int out_size)
{
  const float* x    = (const float*)d_in[0];
  const float* w_in = (const float*)d_in[1];
  const float* gin  = (const float*)d_in[2];
  const float* bin  = (const float*)d_in[3];
  const float* wdw  = (const float*)d_in[4];
  const float* gcv  = (const float*)d_in[5];
  const float* bcv  = (const float*)d_in[6];
  const float* wB   = (const float*)d_in[7];
  const float* wC   = (const float*)d_in[8];
  const float* A    = (const float*)d_in[9];
  const float* Dv   = (const float*)d_in[10];
  const float* wg   = (const float*)d_in[11];
  const float* gg   = (const float*)d_in[12];
  const float* bg   = (const float*)d_in[13];
  const float* wo   = (const float*)d_in[14];
  const float* go   = (const float*)d_in[15];
  const float* bo   = (const float*)d_in[16];
  float* out = (float*)d_out;

  const int SM1 = 73728 + 1024;
  const int SM4 = 57344 + 1024;
  cudaFuncSetAttribute(k_inproj, cudaFuncAttributeMaxDynamicSharedMemorySize, SM1);
  cudaFuncSetAttribute(k_final,  cudaFuncAttributeMaxDynamicSharedMemorySize, SM4);

  k_prep  <<<1, 256>>>(w_in, wg, wo);
  k_inproj<<<dim3(LL/256, BATCH), 256, SM1>>>(x, gin, bin);
  k_dwconv<<<dim3(HH/16, CH, BATCH), 128>>>(wdw, gcv, bcv);
  k_bproj <<<dim3(CUT/64, BATCH), 256>>>(wB);
  k_scan  <<<BATCH*DSTATE, 256>>>(A);
  k_final <<<dim3(LL/128, BATCH), 256, SM4>>>(wC, Dv, gg, bg, go, bo, out);
}

// round 9
// speedup vs baseline: 1.6282x; 1.1366x over previous
#include <cuda_runtime.h>
#include <cuda_fp16.h>
#include <math.h>
#include <stdint.h>

#define BATCH 8
#define CH 64
#define CP 32              // channel pairs
#define HH 512
#define WW 512
#define LL (HH*WW)
#define DSTATE 16
#define CUT 2048
#define BN_EPS 1e-5f

// scratch: xp/xc as packed fp16 channel pairs (u32 = {ch 2c, ch 2c+1})
__device__ unsigned g_xph[(size_t)BATCH*CP*LL];
__device__ unsigned g_xch[(size_t)BATCH*CP*LL];
__device__ float g_Bp[BATCH*DSTATE*CUT];
__device__ float g_Sp[BATCH*DSTATE*CUT];
__device__ float g_S [BATCH*DSTATE];

// pre-swizzled fp16 weight tiles
__device__ __align__(16) unsigned char g_Win[8192];
__device__ __align__(16) unsigned char g_Wg [16384];
__device__ __align__(16) unsigned char g_Wo [8192];

__device__ __forceinline__ float fsig(float x){ return 1.0f/(1.0f+__expf(-x)); }
__device__ __forceinline__ float ftanh(float x){
  x = fminf(fmaxf(x, -15.f), 15.f);
  float e = __expf(2.f*x);
  return __fdividef(e-1.f, e+1.f);
}

#define SW128(o) ((o) ^ (((o)>>3)&0x70))

__device__ __forceinline__ uint32_t smem_u32(const void* p){
  uint32_t a;
  asm("{ .reg .u64 t; cvta.to.shared.u64 t, %1; cvt.u32.u64 %0, t; }"
      : "=r"(a) : "l"(p));
  return a;
}
__device__ __forceinline__ void ldsm4(unsigned r[4], uint32_t a){
  asm volatile("ldmatrix.sync.aligned.m8n8.x4.shared.b16 {%0,%1,%2,%3}, [%4];"
    : "=r"(r[0]),"=r"(r[1]),"=r"(r[2]),"=r"(r[3]) : "r"(a));
}
__device__ __forceinline__ void ldsm2(unsigned r[2], uint32_t a){
  asm volatile("ldmatrix.sync.aligned.m8n8.x2.shared.b16 {%0,%1}, [%2];"
    : "=r"(r[0]),"=r"(r[1]) : "r"(a));
}
__device__ __forceinline__ void mmah(float d[4], const unsigned a[4], const unsigned b0, const unsigned b1){
  asm volatile("mma.sync.aligned.m16n8k16.row.col.f32.f16.f16.f32 "
    "{%0,%1,%2,%3}, {%4,%5,%6,%7}, {%8,%9}, {%0,%1,%2,%3};"
    : "+f"(d[0]),"+f"(d[1]),"+f"(d[2]),"+f"(d[3])
    : "r"(a[0]),"r"(a[1]),"r"(a[2]),"r"(a[3]), "r"(b0),"r"(b1));
}

// fp16 split: hi = rn(v), lo = rn(v - hi)
__device__ __forceinline__ void split2h(float v0, float v1, unsigned& hi, unsigned& lo){
  __half2 hh = __floats2half2_rn(v0, v1);
  hi = *(unsigned*)&hh;
  float r0 = v0 - __half2float(__low2half(hh));
  float r1 = v1 - __half2float(__high2half(hh));
  __half2 ll = __floats2half2_rn(r0, r1);
  lo = *(unsigned*)&ll;
}
__device__ __forceinline__ void unpackh2(unsigned u, float& a, float& b){
  __half2 h = *(__half2*)&u;
  a = __half2float(__low2half(h));
  b = __half2float(__high2half(h));
}

// ---------------------------------------------------------------------------
// K0: one-time weight prep (fp16, SW128-swizzled 128B rows)
// ---------------------------------------------------------------------------
__global__ void k_prep(const float* __restrict__ w_in,
                       const float* __restrict__ wg,
                       const float* __restrict__ wo)
{
  const int tid = threadIdx.x;
  for (int idx=tid; idx<4096; idx+=256){
    int n = idx>>6, k = idx&63;
    unsigned off = SW128((unsigned)(n*128 + k*2));
    *(__half*)(g_Win+off) = __float2half_rn(w_in[idx]);
    *(__half*)(g_Wo +off) = __float2half_rn(wo[idx]);
  }
  for (int idx=tid; idx<8192; idx+=256){
    int n = idx>>6, k = idx&63;
    unsigned off = SW128((unsigned)(n*128 + k*2));
    *(__half*)(g_Wg+off) = __float2half_rn(wg[idx]);
  }
}

// ---------------------------------------------------------------------------
// K1: xp = silu(bn(w_in @ x)) — fp16 2-pass mma, direct half2 epilogue.
// 256 px/block, 256 thr.
// ---------------------------------------------------------------------------
__global__ __launch_bounds__(256,2) void k_inproj(
    const float* __restrict__ x,
    const float* __restrict__ gin, const float* __restrict__ bin)
{
  extern __shared__ char dynraw[];
  char* base = (char*)(((uintptr_t)dynraw + 1023) & ~(uintptr_t)1023);
  char* Ahi = base;            // 32KB
  char* Alo = base + 32768;    // 32KB
  char* Wt  = base + 65536;    // 8KB
  __shared__ float sg[64], sb[64];

  const int tid = threadIdx.x, lane = tid&31, warp = tid>>5;
  const int b = blockIdx.y;
  const long p0 = (long)blockIdx.x*256;

  for (int idx=tid; idx<512; idx+=256)
    ((uint4*)Wt)[idx] = ((const uint4*)g_Win)[idx];
  if (tid<64){ sg[tid]=gin[tid]*rsqrtf(1.f+BN_EPS); sb[tid]=bin[tid]; }

  { // A staging: thread = pixel
    const float* xb = x + (long)b*CH*LL + p0 + tid;
    #pragma unroll
    for (int kb=0;kb<8;kb++){
      unsigned h[4], l[4];
      #pragma unroll
      for (int j=0;j<4;j++)
        split2h(xb[(long)(8*kb+2*j)*LL], xb[(long)(8*kb+2*j+1)*LL], h[j], l[j]);
      unsigned off = SW128((unsigned)(tid*128 + kb*16));
      *(uint4*)(Ahi+off) = make_uint4(h[0],h[1],h[2],h[3]);
      *(uint4*)(Alo+off) = make_uint4(l[0],l[1],l[2],l[3]);
    }
  }
  __syncthreads();

  const uint32_t AhiB=smem_u32(Ahi), AloB=smem_u32(Alo), WtB=smem_u32(Wt);
  float acc[2][8][4];
  #pragma unroll
  for (int mt=0;mt<2;mt++)
    #pragma unroll
    for (int nt=0;nt<8;nt++)
      #pragma unroll
      for (int r=0;r<4;r++) acc[mt][nt][r]=0.f;

  const int Mb = warp*32;
  const int arow = (lane&7) + ((lane>>3)&1)*8;
  const int achk = lane>>4;
  const int brow = lane&7;
  const int bchk = (lane>>3)&1;

  #pragma unroll
  for (int ks=0; ks<4; ks++){
    unsigned ah[2][4], al[2][4];
    #pragma unroll
    for (int mt=0; mt<2; mt++){
      unsigned off = SW128((unsigned)((Mb+16*mt+arow)*128 + (2*ks+achk)*16));
      ldsm4(ah[mt], AhiB+off);
      ldsm4(al[mt], AloB+off);
    }
    #pragma unroll
    for (int nt=0; nt<8; nt++){
      unsigned boff = SW128((unsigned)((8*nt+brow)*128 + (2*ks+bchk)*16));
      unsigned bw[2];
      ldsm2(bw, WtB+boff);
      #pragma unroll
      for (int mt=0;mt<2;mt++){
        mmah(acc[mt][nt], ah[mt], bw[0], bw[1]);
        mmah(acc[mt][nt], al[mt], bw[0], bw[1]);
      }
    }
  }

  // direct paired epilogue: BN + SiLU + half2 store
  unsigned* dst = g_xph + (size_t)b*CP*LL + p0;
  #pragma unroll
  for (int mt=0;mt<2;mt++){
    const int m = Mb + 16*mt + (lane>>2);
    #pragma unroll
    for (int nt=0;nt<8;nt++){
      const int n = 8*nt + 2*(lane&3);
      const size_t rowoff = (size_t)(n>>1)*LL;
      float s0 = sg[n], b0 = sb[n], s1 = sg[n+1], b1 = sb[n+1];
      float v0 = fmaf(acc[mt][nt][0], s0, b0); v0 *= fsig(v0);
      float v1 = fmaf(acc[mt][nt][1], s1, b1); v1 *= fsig(v1);
      float v2 = fmaf(acc[mt][nt][2], s0, b0); v2 *= fsig(v2);
      float v3 = fmaf(acc[mt][nt][3], s1, b1); v3 *= fsig(v3);
      __half2 p01 = __floats2half2_rn(v0, v1);
      __half2 p23 = __floats2half2_rn(v2, v3);
      dst[rowoff + m]     = *(unsigned*)&p01;
      dst[rowoff + m + 8] = *(unsigned*)&p23;
    }
  }
}

// ---------------------------------------------------------------------------
// K2: depthwise 3x3 + BN + SiLU, channel pair per block, half2 data.
// ---------------------------------------------------------------------------
__global__ __launch_bounds__(128) void k_dwconv(
    const float* __restrict__ wdw, const float* __restrict__ gcv,
    const float* __restrict__ bcv)
{
  __shared__ unsigned s[18*512];   // 36 KB, half2 per px
  const int tid = threadIdx.x;
  const int b = blockIdx.z, c2 = blockIdx.y, h0 = blockIdx.x*16;
  const unsigned* src = g_xph + (size_t)(b*CP+c2)*LL;

  #pragma unroll
  for (int r=0;r<18;r++){
    int hh = h0 - 1 + r;
    uint4 v = make_uint4(0u,0u,0u,0u);
    if (hh >= 0 && hh < HH) v = *(const uint4*)(src + (long)hh*WW + (tid<<2));
    *(uint4*)(s + r*512 + (tid<<2)) = v;
  }
  __syncthreads();

  const int c0 = 2*c2, c1 = c0+1;
  float ka[9], kb[9];
  #pragma unroll
  for (int i=0;i<9;i++){ ka[i]=wdw[c0*9+i]; kb[i]=wdw[c1*9+i]; }
  const float rs = rsqrtf(1.0f+BN_EPS);
  const float sc0 = gcv[c0]*rs, be0 = bcv[c0];
  const float sc1 = gcv[c1]*rs, be1 = bcv[c1];
  const int w = tid<<2;
  unsigned* dst = g_xch + (size_t)(b*CP+c2)*LL + (long)h0*WW + w;

  for (int r=0;r<16;r++){
    float a0[3][6], a1[3][6];
    #pragma unroll
    for (int dy=0;dy<3;dy++){
      const unsigned* row = s + (r+dy)*512;
      unsigned e0 = (w>0)? row[w-1] : 0u;
      uint4 m = *(const uint4*)(row + w);
      unsigned e5 = (w<508)? row[w+4] : 0u;
      unpackh2(e0,  a0[dy][0], a1[dy][0]);
      unpackh2(m.x, a0[dy][1], a1[dy][1]);
      unpackh2(m.y, a0[dy][2], a1[dy][2]);
      unpackh2(m.z, a0[dy][3], a1[dy][3]);
      unpackh2(m.w, a0[dy][4], a1[dy][4]);
      unpackh2(e5,  a0[dy][5], a1[dy][5]);
    }
    unsigned o[4];
    #pragma unroll
    for (int j=0;j<4;j++){
      float u = ka[0]*a0[0][j] + ka[1]*a0[0][j+1] + ka[2]*a0[0][j+2]
              + ka[3]*a0[1][j] + ka[4]*a0[1][j+1] + ka[5]*a0[1][j+2]
              + ka[6]*a0[2][j] + ka[7]*a0[2][j+1] + ka[8]*a0[2][j+2];
      float v = kb[0]*a1[0][j] + kb[1]*a1[0][j+1] + kb[2]*a1[0][j+2]
              + kb[3]*a1[1][j] + kb[4]*a1[1][j+1] + kb[5]*a1[1][j+2]
              + kb[6]*a1[2][j] + kb[7]*a1[2][j+1] + kb[8]*a1[2][j+2];
      u = fmaf(u, sc0, be0); u *= fsig(u);
      v = fmaf(v, sc1, be1); v *= fsig(v);
      __half2 p = __floats2half2_rn(u, v);
      o[j] = *(unsigned*)&p;
    }
    *(uint4*)(dst + (long)r*WW) = make_uint4(o[0],o[1],o[2],o[3]);
  }
}

// ---------------------------------------------------------------------------
// K3a: Bp = wB @ xc for k < CUT (paired xc reads)
// ---------------------------------------------------------------------------
__global__ __launch_bounds__(256) void k_bproj(const float* __restrict__ wB)
{
  __shared__ float swB[DSTATE*64];
  __shared__ float red[256][17];
  const int tid = threadIdx.x;
  const int b = blockIdx.y;
  const int px = tid & 63, cg = tid >> 6;
  const int k = blockIdx.x*64 + px;

  for (int idx=tid; idx<DSTATE*64; idx+=256) swB[idx] = wB[idx];
  __syncthreads();

  const unsigned* xcb = g_xch + (size_t)b*CP*LL + k;
  float acc[16];
  #pragma unroll
  for (int s=0;s<16;s++) acc[s]=0.f;
  #pragma unroll
  for (int i=0;i<8;i++){
    int cp = cg*8 + i;
    float xv0, xv1;
    unpackh2(xcb[(size_t)cp*LL], xv0, xv1);
    #pragma unroll
    for (int s=0;s<16;s++){
      acc[s] = fmaf(swB[s*64+2*cp],   xv0, acc[s]);
      acc[s] = fmaf(swB[s*64+2*cp+1], xv1, acc[s]);
    }
  }
  #pragma unroll
  for (int s=0;s<16;s++) red[tid][s] = acc[s];
  __syncthreads();
  if (cg == 0){
    #pragma unroll
    for (int s=0;s<16;s++){
      float v = red[px][s] + red[64+px][s] + red[128+px][s] + red[192+px][s];
      g_Bp[(b*DSTATE+s)*CUT + k] = v;
    }
  }
}

__global__ __launch_bounds__(256) void k_scan(const float* __restrict__ A)
{
  __shared__ float t[CUT];
  const int bs = blockIdx.x;
  const int s = bs & 15;
  const float a = A[s];
  for (int idx = threadIdx.x; idx < CUT; idx += 256)
    t[idx] = g_Bp[bs*CUT + idx] * expf(a * (float)idx);
  __syncthreads();
  if (threadIdx.x == 0){
    float acc = 0.f;
    for (int k=0;k<CUT;k++){ acc += t[k]; t[k] = acc; }
    g_S[bs] = acc;
  }
  __syncthreads();
  for (int idx = threadIdx.x; idx < CUT; idx += 256)
    g_Sp[bs*CUT + idx] = t[idx];
}

// ---------------------------------------------------------------------------
// K4: gate GEMM (1-pass, xp fp16-exact) + combine + out GEMM (2-pass).
// 128 px/block, 256 thr, direct fp32 epilogue.
// ---------------------------------------------------------------------------
__global__ __launch_bounds__(256,2) void k_final(
  const float* __restrict__ wC, const float* __restrict__ Dv,
  const float* __restrict__ gg, const float* __restrict__ bg,
  const float* __restrict__ go, const float* __restrict__ bo,
  float* __restrict__ out)
{
  extern __shared__ char dynraw[];
  char* base = (char*)(((uintptr_t)dynraw + 1023) & ~(uintptr_t)1023);
  char* Ahi = base;            // 16KB (xp, later xg hi)
  char* Alo = base + 16384;    // 16KB (xg lo)
  char* Wg  = base + 32768;    // 16KB
  char* Wo  = base + 49152;    // 8KB
  __shared__ float s_gsc[128], s_gbe[128], s_dvec[64], s_cvec[64], s_osc[64], s_obe[64];
  __shared__ float s_wC[64*16];

  const int tid = threadIdx.x, lane = tid&31, warp = tid>>5;
  const int b = blockIdx.y;
  const long p0 = (long)blockIdx.x*128;
  const bool boundary = (p0 < CUT);
  const float rs = rsqrtf(1.0f+BN_EPS);

  for (int idx=tid; idx<1024; idx+=256)
    ((uint4*)Wg)[idx] = ((const uint4*)g_Wg)[idx];
  for (int idx=tid; idx<512; idx+=256)
    ((uint4*)Wo)[idx] = ((const uint4*)g_Wo)[idx];
  if (tid < 128){ s_gsc[tid] = gg[tid]*rs; s_gbe[tid] = bg[tid]; }
  for (int idx=tid; idx<1024; idx+=256) s_wC[idx] = wC[idx];
  if (tid < 64){
    s_dvec[tid] = Dv[tid];
    s_osc[tid]  = go[tid]*rs;
    s_obe[tid]  = bo[tid];
    float c = 0.f;
    #pragma unroll
    for (int s=0;s<16;s++) c = fmaf(wC[tid*16+s], g_S[b*16+s], c);
    s_cvec[tid] = c;
  }

  { // A staging from packed fp16 xp: plain u32 gathers, no split
    const int px = tid & 127, half = tid >> 7;
    const unsigned* xpb = g_xph + (size_t)b*CP*LL + p0 + px;
    #pragma unroll
    for (int j=0;j<4;j++){
      const int cp0 = half*16 + j*4;
      uint4 v;
      v.x = xpb[(size_t)(cp0+0)*LL];
      v.y = xpb[(size_t)(cp0+1)*LL];
      v.z = xpb[(size_t)(cp0+2)*LL];
      v.w = xpb[(size_t)(cp0+3)*LL];
      unsigned off = SW128((unsigned)(px*128 + (half*4+j)*16));
      *(uint4*)(Ahi+off) = v;
    }
  }
  __syncthreads();

  const uint32_t AhiB=smem_u32(Ahi), AloB=smem_u32(Alo),
                 WgB=smem_u32(Wg), WoB=smem_u32(Wo);
  const int Mb = warp*16;
  const int arow = (lane&7) + ((lane>>3)&1)*8;
  const int achk = lane>>4;
  const int brow = lane&7;
  const int bchk = (lane>>3)&1;

  // preload A fragments (xp, exact fp16): 16 regs
  unsigned ah[4][4];
  #pragma unroll
  for (int ks=0; ks<4; ks++){
    unsigned aoff = SW128((unsigned)((Mb+arow)*128 + (2*ks+achk)*16));
    ldsm4(ah[ks], AhiB+aoff);
  }

  // gate GEMM (1-pass) + combine, streamed per nt
  const unsigned* xcb = g_xch + (size_t)b*CP*LL + p0;
  #pragma unroll
  for (int nt=0; nt<8; nt++){
    float accg[4] = {0.f,0.f,0.f,0.f};
    float accs[4] = {0.f,0.f,0.f,0.f};
    #pragma unroll
    for (int ks=0; ks<4; ks++){
      unsigned bgo = SW128((unsigned)((8*nt+brow)*128 + (2*ks+bchk)*16));
      unsigned bso = SW128((unsigned)((8*(nt+8)+brow)*128 + (2*ks+bchk)*16));
      unsigned bw[2];
      ldsm2(bw, WgB+bgo);
      mmah(accg, ah[ks], bw[0], bw[1]);
      ldsm2(bw, WgB+bso);
      mmah(accs, ah[ks], bw[0], bw[1]);
    }
    const int ch0 = 8*nt + 2*(lane&3), ch1 = ch0+1;
    const float dv0 = s_dvec[ch0], dv1 = s_dvec[ch1];
    const size_t xrow = (size_t)(ch0>>1)*LL;
    #pragma unroll
    for (int rp=0; rp<2; rp++){
      const int pxl = Mb + (lane>>2) + rp*8;
      float base0, base1;
      if (boundary){
        const long p = p0 + pxl;
        float d0=0.f, d1=0.f;
        for (int s=0;s<16;s++){
          float sv = g_Sp[(b*DSTATE+s)*CUT + p];
          d0 = fmaf(s_wC[ch0*16+s], sv, d0);
          d1 = fmaf(s_wC[ch1*16+s], sv, d1);
        }
        base0=d0; base1=d1;
      } else { base0 = s_cvec[ch0]; base1 = s_cvec[ch1]; }
      float xc0, xc1;
      unpackh2(xcb[xrow + pxl], xc0, xc1);
      float g0 = fmaf(accg[2*rp],   s_gsc[ch0], s_gbe[ch0]);
      float g1 = fmaf(accg[2*rp+1], s_gsc[ch1], s_gbe[ch1]);
      float h0 = fmaf(accs[2*rp],   s_gsc[64+ch0], s_gbe[64+ch0]);
      float h1 = fmaf(accs[2*rp+1], s_gsc[64+ch1], s_gbe[64+ch1]);
      float v0 = fsig(g0)*(fmaf(dv0, xc0, base0) + ftanh(h0));
      float v1 = fsig(g1)*(fmaf(dv1, xc1, base1) + ftanh(h1));
      unsigned hi, lo;
      split2h(v0, v1, hi, lo);
      unsigned off = SW128((unsigned)(pxl*128 + ch0*2));
      *(unsigned*)(Ahi+off) = hi;
      *(unsigned*)(Alo+off) = lo;
    }
  }
  __syncwarp();   // rows [Mb, Mb+16) are warp-private

  // reload A fragments (xg hi/lo)
  unsigned al[4][4];
  #pragma unroll
  for (int ks=0; ks<4; ks++){
    unsigned aoff = SW128((unsigned)((Mb+arow)*128 + (2*ks+achk)*16));
    ldsm4(ah[ks], AhiB+aoff);
    ldsm4(al[ks], AloB+aoff);
  }
  // out GEMM (2-pass)
  float acc2[8][4];
  #pragma unroll
  for (int nt=0;nt<8;nt++)
    #pragma unroll
    for (int r=0;r<4;r++) acc2[nt][r]=0.f;
  #pragma unroll
  for (int ks=0; ks<4; ks++){
    #pragma unroll
    for (int nt=0; nt<8; nt++){
      unsigned boff = SW128((unsigned)((8*nt+brow)*128 + (2*ks+bchk)*16));
      unsigned bw[2];
      ldsm2(bw, WoB+boff);
      mmah(acc2[nt], ah[ks], bw[0], bw[1]);
      mmah(acc2[nt], al[ks], bw[0], bw[1]);
    }
  }

  // direct fp32 epilogue
  float* dst = out + (long)b*CH*LL + p0;
  const int m = Mb + (lane>>2);
  #pragma unroll
  for (int nt=0;nt<8;nt++){
    const int n = 8*nt + 2*(lane&3);
    float s0 = s_osc[n], b0 = s_obe[n], s1 = s_osc[n+1], b1 = s_obe[n+1];
    dst[(long)n*LL + m]         = fmaf(acc2[nt][0], s0, b0);
    dst[(long)(n+1)*LL + m]     = fmaf(acc2[nt][1], s1, b1);
    dst[(long)n*LL + m + 8]     = fmaf(acc2[nt][2], s0, b0);
    dst[(long)(n+1)*LL + m + 8] = fmaf(acc2[nt][3], s1, b1);
  }
}

// ---------------------------------------------------------------------------
extern "C" void kernel_launch(void* const* d_in, const int* in_sizes, int n_in,
                              void* d_out, int out_size)
{
  const float* x    = (const float*)d_in[0];
  const float* w_in = (const float*)d_in[1];
  const float* gin  = (const float*)d_in[2];
  const float* bin  = (const float*)d_in[3];
  const float* wdw  = (const float*)d_in[4];
  const float* gcv  = (const float*)d_in[5];
  const float* bcv  = (const float*)d_in[6];
  const float* wB   = (const float*)d_in[7];
  const float* wC   = (const float*)d_in[8];
  const float* A    = (const float*)d_in[9];
  const float* Dv   = (const float*)d_in[10];
  const float* wg   = (const float*)d_in[11];
  const float* gg   = (const float*)d_in[12];
  const float* bg   = (const float*)d_in[13];
  const float* wo   = (const float*)d_in[14];
  const float* go   = (const float*)d_in[15];
  const float* bo   = (const float*)d_in[16];
  float* out = (float*)d_out;

  const int SM1 = 73728 + 1024;
  const int SM4 = 57344 + 1024;
  cudaFuncSetAttribute(k_inproj, cudaFuncAttributeMaxDynamicSharedMemorySize, SM1);
  cudaFuncSetAttribute(k_final,  cudaFuncAttributeMaxDynamicSharedMemorySize, SM4);

  k_prep  <<<1, 256>>>(w_in, wg, wo);
  k_inproj<<<dim3(LL/256, BATCH), 256, SM1>>>(x, gin, bin);
  k_dwconv<<<dim3(HH/16, CP, BATCH), 128>>>(wdw, gcv, bcv);
  k_bproj <<<dim3(CUT/64, BATCH), 256>>>(wB);
  k_scan  <<<BATCH*DSTATE, 256>>>(A);
  k_final <<<dim3(LL/128, BATCH), 256, SM4>>>(wC, Dv, gg, bg, go, bo, out);
}

// round 10
// speedup vs baseline: 1.9449x; 1.1945x over previous
#include <cuda_runtime.h>
#include <cuda_fp16.h>
#include <math.h>
#include <stdint.h>

#define BATCH 8
#define CH 64
#define CP 32              // channel pairs
#define HH 512
#define WW 512
#define LL (HH*WW)
#define DSTATE 16
#define CUT 2048
#define BN_EPS 1e-5f

// scratch: xp/xc as packed fp16 channel pairs (u32 = {ch 2c, ch 2c+1})
__device__ unsigned g_xph[(size_t)BATCH*CP*LL];
__device__ unsigned g_xch[(size_t)BATCH*CP*LL];
__device__ float g_Bp[BATCH*DSTATE*CUT];
__device__ float g_Sp[BATCH*DSTATE*CUT];
__device__ float g_S [BATCH*DSTATE];

// pre-swizzled fp16 weight tiles
__device__ __align__(16) unsigned char g_Win[8192];
__device__ __align__(16) unsigned char g_Wg [16384];
__device__ __align__(16) unsigned char g_Wo [8192];

__device__ __forceinline__ float fsig(float x){ return 1.0f/(1.0f+__expf(-x)); }
__device__ __forceinline__ float ftanh(float x){
  x = fminf(fmaxf(x, -15.f), 15.f);
  float e = __expf(2.f*x);
  return __fdividef(e-1.f, e+1.f);
}

#define SW128(o) ((o) ^ (((o)>>3)&0x70))

__device__ __forceinline__ uint32_t smem_u32(const void* p){
  uint32_t a;
  asm("{ .reg .u64 t; cvta.to.shared.u64 t, %1; cvt.u32.u64 %0, t; }"
      : "=r"(a) : "l"(p));
  return a;
}
__device__ __forceinline__ void ldsm4(unsigned r[4], uint32_t a){
  asm volatile("ldmatrix.sync.aligned.m8n8.x4.shared.b16 {%0,%1,%2,%3}, [%4];"
    : "=r"(r[0]),"=r"(r[1]),"=r"(r[2]),"=r"(r[3]) : "r"(a));
}
__device__ __forceinline__ void ldsm2(unsigned r[2], uint32_t a){
  asm volatile("ldmatrix.sync.aligned.m8n8.x2.shared.b16 {%0,%1}, [%2];"
    : "=r"(r[0]),"=r"(r[1]) : "r"(a));
}
__device__ __forceinline__ void mmah(float d[4], const unsigned a[4], const unsigned b0, const unsigned b1){
  asm volatile("mma.sync.aligned.m16n8k16.row.col.f32.f16.f16.f32 "
    "{%0,%1,%2,%3}, {%4,%5,%6,%7}, {%8,%9}, {%0,%1,%2,%3};"
    : "+f"(d[0]),"+f"(d[1]),"+f"(d[2]),"+f"(d[3])
    : "r"(a[0]),"r"(a[1]),"r"(a[2]),"r"(a[3]), "r"(b0),"r"(b1));
}
__device__ __forceinline__ void unpackh2(unsigned u, float& a, float& b){
  __half2 h = *(__half2*)&u;
  a = __half2float(__low2half(h));
  b = __half2float(__high2half(h));
}
__device__ __forceinline__ unsigned packh2(float a, float b){
  __half2 h = __floats2half2_rn(a, b);
  return *(unsigned*)&h;
}

// ---------------------------------------------------------------------------
// K0: one-time weight prep (fp16, SW128-swizzled 128B rows)
// ---------------------------------------------------------------------------
__global__ void k_prep(const float* __restrict__ w_in,
                       const float* __restrict__ wg,
                       const float* __restrict__ wo)
{
  const int tid = threadIdx.x;
  for (int idx=tid; idx<4096; idx+=256){
    int n = idx>>6, k = idx&63;
    unsigned off = SW128((unsigned)(n*128 + k*2));
    *(__half*)(g_Win+off) = __float2half_rn(w_in[idx]);
    *(__half*)(g_Wo +off) = __float2half_rn(wo[idx]);
  }
  for (int idx=tid; idx<8192; idx+=256){
    int n = idx>>6, k = idx&63;
    unsigned off = SW128((unsigned)(n*128 + k*2));
    *(__half*)(g_Wg+off) = __float2half_rn(wg[idx]);
  }
}

// ---------------------------------------------------------------------------
// K1: xp = silu(bn(w_in @ x)) — fp16 1-pass mma, direct half2 epilogue.
// 256 px/block, 256 thr.
// ---------------------------------------------------------------------------
__global__ __launch_bounds__(256,2) void k_inproj(
    const float* __restrict__ x,
    const float* __restrict__ gin, const float* __restrict__ bin)
{
  extern __shared__ char dynraw[];
  char* base = (char*)(((uintptr_t)dynraw + 1023) & ~(uintptr_t)1023);
  char* Ah = base;            // 32KB
  char* Wt = base + 32768;    // 8KB
  __shared__ float sg[64], sb[64];

  const int tid = threadIdx.x, lane = tid&31, warp = tid>>5;
  const int b = blockIdx.y;
  const long p0 = (long)blockIdx.x*256;

  for (int idx=tid; idx<512; idx+=256)
    ((uint4*)Wt)[idx] = ((const uint4*)g_Win)[idx];
  if (tid<64){ sg[tid]=gin[tid]*rsqrtf(1.f+BN_EPS); sb[tid]=bin[tid]; }

  { // A staging: thread = pixel, single fp16 pass
    const float* xb = x + (long)b*CH*LL + p0 + tid;
    #pragma unroll
    for (int kb=0;kb<8;kb++){
      unsigned h[4];
      #pragma unroll
      for (int j=0;j<4;j++)
        h[j] = packh2(xb[(long)(8*kb+2*j)*LL], xb[(long)(8*kb+2*j+1)*LL]);
      unsigned off = SW128((unsigned)(tid*128 + kb*16));
      *(uint4*)(Ah+off) = make_uint4(h[0],h[1],h[2],h[3]);
    }
  }
  __syncthreads();

  const uint32_t AhB=smem_u32(Ah), WtB=smem_u32(Wt);
  float acc[2][8][4];
  #pragma unroll
  for (int mt=0;mt<2;mt++)
    #pragma unroll
    for (int nt=0;nt<8;nt++)
      #pragma unroll
      for (int r=0;r<4;r++) acc[mt][nt][r]=0.f;

  const int Mb = warp*32;
  const int arow = (lane&7) + ((lane>>3)&1)*8;
  const int achk = lane>>4;
  const int brow = lane&7;
  const int bchk = (lane>>3)&1;

  #pragma unroll
  for (int ks=0; ks<4; ks++){
    unsigned ah[2][4];
    #pragma unroll
    for (int mt=0; mt<2; mt++){
      unsigned off = SW128((unsigned)((Mb+16*mt+arow)*128 + (2*ks+achk)*16));
      ldsm4(ah[mt], AhB+off);
    }
    #pragma unroll
    for (int nt=0; nt<8; nt++){
      unsigned boff = SW128((unsigned)((8*nt+brow)*128 + (2*ks+bchk)*16));
      unsigned bw[2];
      ldsm2(bw, WtB+boff);
      #pragma unroll
      for (int mt=0;mt<2;mt++)
        mmah(acc[mt][nt], ah[mt], bw[0], bw[1]);
    }
  }

  // direct paired epilogue: BN + SiLU + half2 store
  unsigned* dst = g_xph + (size_t)b*CP*LL + p0;
  #pragma unroll
  for (int mt=0;mt<2;mt++){
    const int m = Mb + 16*mt + (lane>>2);
    #pragma unroll
    for (int nt=0;nt<8;nt++){
      const int n = 8*nt + 2*(lane&3);
      const size_t rowoff = (size_t)(n>>1)*LL;
      float s0 = sg[n], b0 = sb[n], s1 = sg[n+1], b1 = sb[n+1];
      float v0 = fmaf(acc[mt][nt][0], s0, b0); v0 *= fsig(v0);
      float v1 = fmaf(acc[mt][nt][1], s1, b1); v1 *= fsig(v1);
      float v2 = fmaf(acc[mt][nt][2], s0, b0); v2 *= fsig(v2);
      float v3 = fmaf(acc[mt][nt][3], s1, b1); v3 *= fsig(v3);
      dst[rowoff + m]     = packh2(v0, v1);
      dst[rowoff + m + 8] = packh2(v2, v3);
    }
  }
}

// ---------------------------------------------------------------------------
// K2: depthwise 3x3 + BN + SiLU, channel pair per block, half2 data.
// ---------------------------------------------------------------------------
__global__ __launch_bounds__(128) void k_dwconv(
    const float* __restrict__ wdw, const float* __restrict__ gcv,
    const float* __restrict__ bcv)
{
  __shared__ unsigned s[18*512];   // 36 KB, half2 per px
  const int tid = threadIdx.x;
  const int b = blockIdx.z, c2 = blockIdx.y, h0 = blockIdx.x*16;
  const unsigned* src = g_xph + (size_t)(b*CP+c2)*LL;

  #pragma unroll
  for (int r=0;r<18;r++){
    int hh = h0 - 1 + r;
    uint4 v = make_uint4(0u,0u,0u,0u);
    if (hh >= 0 && hh < HH) v = *(const uint4*)(src + (long)hh*WW + (tid<<2));
    *(uint4*)(s + r*512 + (tid<<2)) = v;
  }
  __syncthreads();

  const int c0 = 2*c2, c1 = c0+1;
  float ka[9], kb[9];
  #pragma unroll
  for (int i=0;i<9;i++){ ka[i]=wdw[c0*9+i]; kb[i]=wdw[c1*9+i]; }
  const float rs = rsqrtf(1.0f+BN_EPS);
  const float sc0 = gcv[c0]*rs, be0 = bcv[c0];
  const float sc1 = gcv[c1]*rs, be1 = bcv[c1];
  const int w = tid<<2;
  unsigned* dst = g_xch + (size_t)(b*CP+c2)*LL + (long)h0*WW + w;

  for (int r=0;r<16;r++){
    float a0[3][6], a1[3][6];
    #pragma unroll
    for (int dy=0;dy<3;dy++){
      const unsigned* row = s + (r+dy)*512;
      unsigned e0 = (w>0)? row[w-1] : 0u;
      uint4 m = *(const uint4*)(row + w);
      unsigned e5 = (w<508)? row[w+4] : 0u;
      unpackh2(e0,  a0[dy][0], a1[dy][0]);
      unpackh2(m.x, a0[dy][1], a1[dy][1]);
      unpackh2(m.y, a0[dy][2], a1[dy][2]);
      unpackh2(m.z, a0[dy][3], a1[dy][3]);
      unpackh2(m.w, a0[dy][4], a1[dy][4]);
      unpackh2(e5,  a0[dy][5], a1[dy][5]);
    }
    unsigned o[4];
    #pragma unroll
    for (int j=0;j<4;j++){
      float u = ka[0]*a0[0][j] + ka[1]*a0[0][j+1] + ka[2]*a0[0][j+2]
              + ka[3]*a0[1][j] + ka[4]*a0[1][j+1] + ka[5]*a0[1][j+2]
              + ka[6]*a0[2][j] + ka[7]*a0[2][j+1] + ka[8]*a0[2][j+2];
      float v = kb[0]*a1[0][j] + kb[1]*a1[0][j+1] + kb[2]*a1[0][j+2]
              + kb[3]*a1[1][j] + kb[4]*a1[1][j+1] + kb[5]*a1[1][j+2]
              + kb[6]*a1[2][j] + kb[7]*a1[2][j+1] + kb[8]*a1[2][j+2];
      u = fmaf(u, sc0, be0); u *= fsig(u);
      v = fmaf(v, sc1, be1); v *= fsig(v);
      o[j] = packh2(u, v);
    }
    *(uint4*)(dst + (long)r*WW) = make_uint4(o[0],o[1],o[2],o[3]);
  }
}

// ---------------------------------------------------------------------------
// K3a: Bp = wB @ xc for k < CUT (paired xc reads)
// ---------------------------------------------------------------------------
__global__ __launch_bounds__(256) void k_bproj(const float* __restrict__ wB)
{
  __shared__ float swB[DSTATE*64];
  __shared__ float red[256][17];
  const int tid = threadIdx.x;
  const int b = blockIdx.y;
  const int px = tid & 63, cg = tid >> 6;
  const int k = blockIdx.x*64 + px;

  for (int idx=tid; idx<DSTATE*64; idx+=256) swB[idx] = wB[idx];
  __syncthreads();

  const unsigned* xcb = g_xch + (size_t)b*CP*LL + k;
  float acc[16];
  #pragma unroll
  for (int s=0;s<16;s++) acc[s]=0.f;
  #pragma unroll
  for (int i=0;i<8;i++){
    int cp = cg*8 + i;
    float xv0, xv1;
    unpackh2(xcb[(size_t)cp*LL], xv0, xv1);
    #pragma unroll
    for (int s=0;s<16;s++){
      acc[s] = fmaf(swB[s*64+2*cp],   xv0, acc[s]);
      acc[s] = fmaf(swB[s*64+2*cp+1], xv1, acc[s]);
    }
  }
  #pragma unroll
  for (int s=0;s<16;s++) red[tid][s] = acc[s];
  __syncthreads();
  if (cg == 0){
    #pragma unroll
    for (int s=0;s<16;s++){
      float v = red[px][s] + red[64+px][s] + red[128+px][s] + red[192+px][s];
      g_Bp[(b*DSTATE+s)*CUT + k] = v;
    }
  }
}

__global__ __launch_bounds__(256) void k_scan(const float* __restrict__ A)
{
  __shared__ float t[CUT];
  const int bs = blockIdx.x;
  const int s = bs & 15;
  const float a = A[s];
  for (int idx = threadIdx.x; idx < CUT; idx += 256)
    t[idx] = g_Bp[bs*CUT + idx] * expf(a * (float)idx);
  __syncthreads();
  if (threadIdx.x == 0){
    float acc = 0.f;
    for (int k=0;k<CUT;k++){ acc += t[k]; t[k] = acc; }
    g_S[bs] = acc;
  }
  __syncthreads();
  for (int idx = threadIdx.x; idx < CUT; idx += 256)
    g_Sp[bs*CUT + idx] = t[idx];
}

// ---------------------------------------------------------------------------
// K4: gate GEMM (1-pass) + combine + out GEMM (1-pass).
// 128 px/block, 256 thr, 3 blocks/SM, direct fp32 epilogue.
// ---------------------------------------------------------------------------
__global__ __launch_bounds__(256,3) void k_final(
  const float* __restrict__ wC, const float* __restrict__ Dv,
  const float* __restrict__ gg, const float* __restrict__ bg,
  const float* __restrict__ go, const float* __restrict__ bo,
  float* __restrict__ out)
{
  extern __shared__ char dynraw[];
  char* base = (char*)(((uintptr_t)dynraw + 1023) & ~(uintptr_t)1023);
  char* Ah = base;            // 16KB (xp, later xg)
  char* Wg = base + 16384;    // 16KB
  char* Wo = base + 32768;    // 8KB   (total 40KB)
  __shared__ float s_gsc[128], s_gbe[128], s_dvec[64], s_cvec[64], s_osc[64], s_obe[64];
  __shared__ float s_wC[64*16];

  const int tid = threadIdx.x, lane = tid&31, warp = tid>>5;
  const int b = blockIdx.y;
  const long p0 = (long)blockIdx.x*128;
  const bool boundary = (p0 < CUT);
  const float rs = rsqrtf(1.0f+BN_EPS);

  for (int idx=tid; idx<1024; idx+=256)
    ((uint4*)Wg)[idx] = ((const uint4*)g_Wg)[idx];
  for (int idx=tid; idx<512; idx+=256)
    ((uint4*)Wo)[idx] = ((const uint4*)g_Wo)[idx];
  if (tid < 128){ s_gsc[tid] = gg[tid]*rs; s_gbe[tid] = bg[tid]; }
  for (int idx=tid; idx<1024; idx+=256) s_wC[idx] = wC[idx];
  if (tid < 64){
    s_dvec[tid] = Dv[tid];
    s_osc[tid]  = go[tid]*rs;
    s_obe[tid]  = bo[tid];
    float c = 0.f;
    #pragma unroll
    for (int s=0;s<16;s++) c = fmaf(wC[tid*16+s], g_S[b*16+s], c);
    s_cvec[tid] = c;
  }

  { // A staging from packed fp16 xp: plain u32 gathers
    const int px = tid & 127, half = tid >> 7;
    const unsigned* xpb = g_xph + (size_t)b*CP*LL + p0 + px;
    #pragma unroll
    for (int j=0;j<4;j++){
      const int cp0 = half*16 + j*4;
      uint4 v;
      v.x = xpb[(size_t)(cp0+0)*LL];
      v.y = xpb[(size_t)(cp0+1)*LL];
      v.z = xpb[(size_t)(cp0+2)*LL];
      v.w = xpb[(size_t)(cp0+3)*LL];
      unsigned off = SW128((unsigned)(px*128 + (half*4+j)*16));
      *(uint4*)(Ah+off) = v;
    }
  }
  __syncthreads();

  const uint32_t AhB=smem_u32(Ah), WgB=smem_u32(Wg), WoB=smem_u32(Wo);
  const int Mb = warp*16;
  const int arow = (lane&7) + ((lane>>3)&1)*8;
  const int achk = lane>>4;
  const int brow = lane&7;
  const int bchk = (lane>>3)&1;

  // preload A fragments (xp, exact fp16): 16 regs
  unsigned ah[4][4];
  #pragma unroll
  for (int ks=0; ks<4; ks++){
    unsigned aoff = SW128((unsigned)((Mb+arow)*128 + (2*ks+achk)*16));
    ldsm4(ah[ks], AhB+aoff);
  }

  // gate GEMM (1-pass) + combine, streamed per nt
  const unsigned* xcb = g_xch + (size_t)b*CP*LL + p0;
  #pragma unroll
  for (int nt=0; nt<8; nt++){
    float accg[4] = {0.f,0.f,0.f,0.f};
    float accs[4] = {0.f,0.f,0.f,0.f};
    #pragma unroll
    for (int ks=0; ks<4; ks++){
      unsigned bgo = SW128((unsigned)((8*nt+brow)*128 + (2*ks+bchk)*16));
      unsigned bso = SW128((unsigned)((8*(nt+8)+brow)*128 + (2*ks+bchk)*16));
      unsigned bw[2];
      ldsm2(bw, WgB+bgo);
      mmah(accg, ah[ks], bw[0], bw[1]);
      ldsm2(bw, WgB+bso);
      mmah(accs, ah[ks], bw[0], bw[1]);
    }
    const int ch0 = 8*nt + 2*(lane&3), ch1 = ch0+1;
    const float dv0 = s_dvec[ch0], dv1 = s_dvec[ch1];
    const size_t xrow = (size_t)(ch0>>1)*LL;
    #pragma unroll
    for (int rp=0; rp<2; rp++){
      const int pxl = Mb + (lane>>2) + rp*8;
      float base0, base1;
      if (boundary){
        const long p = p0 + pxl;
        float d0=0.f, d1=0.f;
        for (int s=0;s<16;s++){
          float sv = g_Sp[(b*DSTATE+s)*CUT + p];
          d0 = fmaf(s_wC[ch0*16+s], sv, d0);
          d1 = fmaf(s_wC[ch1*16+s], sv, d1);
        }
        base0=d0; base1=d1;
      } else { base0 = s_cvec[ch0]; base1 = s_cvec[ch1]; }
      float xc0, xc1;
      unpackh2(xcb[xrow + pxl], xc0, xc1);
      float g0 = fmaf(accg[2*rp],   s_gsc[ch0], s_gbe[ch0]);
      float g1 = fmaf(accg[2*rp+1], s_gsc[ch1], s_gbe[ch1]);
      float h0 = fmaf(accs[2*rp],   s_gsc[64+ch0], s_gbe[64+ch0]);
      float h1 = fmaf(accs[2*rp+1], s_gsc[64+ch1], s_gbe[64+ch1]);
      float v0 = fsig(g0)*(fmaf(dv0, xc0, base0) + ftanh(h0));
      float v1 = fsig(g1)*(fmaf(dv1, xc1, base1) + ftanh(h1));
      unsigned off = SW128((unsigned)(pxl*128 + ch0*2));
      *(unsigned*)(Ah+off) = packh2(v0, v1);
    }
  }
  __syncwarp();   // rows [Mb, Mb+16) are warp-private

  // reload A fragments (xg, 1-pass fp16)
  #pragma unroll
  for (int ks=0; ks<4; ks++){
    unsigned aoff = SW128((unsigned)((Mb+arow)*128 + (2*ks+achk)*16));
    ldsm4(ah[ks], AhB+aoff);
  }
  // out GEMM (1-pass)
  float acc2[8][4];
  #pragma unroll
  for (int nt=0;nt<8;nt++)
    #pragma unroll
    for (int r=0;r<4;r++) acc2[nt][r]=0.f;
  #pragma unroll
  for (int ks=0; ks<4; ks++){
    #pragma unroll
    for (int nt=0; nt<8; nt++){
      unsigned boff = SW128((unsigned)((8*nt+brow)*128 + (2*ks+bchk)*16));
      unsigned bw[2];
      ldsm2(bw, WoB+boff);
      mmah(acc2[nt], ah[ks], bw[0], bw[1]);
    }
  }

  // direct fp32 epilogue
  float* dst = out + (long)b*CH*LL + p0;
  const int m = Mb + (lane>>2);
  #pragma unroll
  for (int nt=0;nt<8;nt++){
    const int n = 8*nt + 2*(lane&3);
    float s0 = s_osc[n], b0 = s_obe[n], s1 = s_osc[n+1], b1 = s_obe[n+1];
    dst[(long)n*LL + m]         = fmaf(acc2[nt][0], s0, b0);
    dst[(long)(n+1)*LL + m]     = fmaf(acc2[nt][1], s1, b1);
    dst[(long)n*LL + m + 8]     = fmaf(acc2[nt][2], s0, b0);
    dst[(long)(n+1)*LL + m + 8] = fmaf(acc2[nt][3], s1, b1);
  }
}

// ---------------------------------------------------------------------------
extern "C" void kernel_launch(void* const* d_in, const int* in_sizes, int n_in,
                              void* d_out, int out_size)
{
  const float* x    = (const float*)d_in[0];
  const float* w_in = (const float*)d_in[1];
  const float* gin  = (const float*)d_in[2];
  const float* bin  = (const float*)d_in[3];
  const float* wdw  = (const float*)d_in[4];
  const float* gcv  = (const float*)d_in[5];
  const float* bcv  = (const float*)d_in[6];
  const float* wB   = (const float*)d_in[7];
  const float* wC   = (const float*)d_in[8];
  const float* A    = (const float*)d_in[9];
  const float* Dv   = (const float*)d_in[10];
  const float* wg   = (const float*)d_in[11];
  const float* gg   = (const float*)d_in[12];
  const float* bg   = (const float*)d_in[13];
  const float* wo   = (const float*)d_in[14];
  const float* go   = (const float*)d_in[15];
  const float* bo   = (const float*)d_in[16];
  float* out = (float*)d_out;

  const int SM1 = 40960 + 1024;
  const int SM4 = 40960 + 1024;
  cudaFuncSetAttribute(k_inproj, cudaFuncAttributeMaxDynamicSharedMemorySize, SM1);
  cudaFuncSetAttribute(k_final,  cudaFuncAttributeMaxDynamicSharedMemorySize, SM4);

  k_prep  <<<1, 256>>>(w_in, wg, wo);
  k_inproj<<<dim3(LL/256, BATCH), 256, SM1>>>(x, gin, bin);
  k_dwconv<<<dim3(HH/16, CP, BATCH), 128>>>(wdw, gcv, bcv);
  k_bproj <<<dim3(CUT/64, BATCH), 256>>>(wB);
  k_scan  <<<BATCH*DSTATE, 256>>>(A);
  k_final <<<dim3(LL/128, BATCH), 256, SM4>>>(wC, Dv, gg, bg, go, bo, out);
}